// round 14
// baseline (speedup 1.0000x reference)
#include <cuda_runtime.h>
#include <cuda_fp16.h>
#include <math.h>
#include <stdint.h>

// Problem constants
#define BB 4
#define SS 2048
#define DD 1024
#define HH 16
#define HDIM 64
#define FFN 2048
#define NTOK (BB*SS)          // 8192

// ---------------- scratch (device globals: allocation-free) ----------------
__device__ float  g_X   [NTOK * DD];          // fp32 residual stream
__device__ float  g_O   [NTOK * DD];          // fp32 gemm output
__device__ __half g_X16 [NTOK * DD];          // fp16 activation copy
__device__ __half g_QKV16[NTOK * 3 * DD];
__device__ __half g_Vt16 [BB * HH * HDIM * SS];  // V transposed [b,h,dim,seq]
__device__ __half g_AO16 [NTOK * DD];
__device__ __half g_H16  [NTOK * FFN];
__device__ __half g_Wq16 [3 * DD * DD];
__device__ __half g_Wf16 [DD * DD];
__device__ __half g_W116 [FFN * DD];
__device__ __half g_W216 [DD * FFN];
__device__ float  g_part[BB * 16 * DD];
__device__ float  g_pool[BB * DD];
__device__ float  g_hh  [BB * DD];

__device__ __forceinline__ float gelu_exact(float v) {
    return 0.5f * v * (1.0f + erff(v * 0.7071067811865476f));
}

__device__ __forceinline__ uint32_t smem_u32(const void* p) {
    return (uint32_t)__cvta_generic_to_shared(p);
}
__device__ __forceinline__ void cp16(uint32_t dst, const void* src) {
    asm volatile("cp.async.cg.shared.global [%0], [%1], 16;" :: "r"(dst), "l"(src));
}
__device__ __forceinline__ void cp_commit() {
    asm volatile("cp.async.commit_group;");
}
template<int N>
__device__ __forceinline__ void cp_wait() {
    asm volatile("cp.async.wait_group %0;" :: "n"(N));
}

// fp16 MMA, fp32 accumulate: m16n8k16
__device__ __forceinline__ void mma_f16(float* d, const uint32_t* a, uint32_t b0, uint32_t b1) {
    asm volatile(
        "mma.sync.aligned.m16n8k16.row.col.f32.f16.f16.f32 "
        "{%0,%1,%2,%3}, {%4,%5,%6,%7}, {%8,%9}, {%0,%1,%2,%3};\n"
        : "+f"(d[0]), "+f"(d[1]), "+f"(d[2]), "+f"(d[3])
        : "r"(a[0]), "r"(a[1]), "r"(a[2]), "r"(a[3]), "r"(b0), "r"(b1));
}

// non-trans ldmatrix x4: A-type ([m][k] rows) and B-type stored as [n][k] rows
__device__ __forceinline__ void ldsm_x4(uint32_t& r0, uint32_t& r1, uint32_t& r2, uint32_t& r3,
                                        uint32_t addr) {
    asm volatile("ldmatrix.sync.aligned.m8n8.x4.shared.b16 {%0,%1,%2,%3}, [%4];"
                 : "=r"(r0), "=r"(r1), "=r"(r2), "=r"(r3) : "r"(addr));
}

__device__ __forceinline__ uint32_t pack_half2(float a, float b) {
    __half2 h = __floats2half2_rn(a, b);
    uint32_t u;
    memcpy(&u, &h, 4);
    return u;
}

// ---------------- fp32 -> fp16 weight conversion ----------------
__global__ void f2h_kernel(const float* __restrict__ in, __half* __restrict__ out, int n) {
    int i = (blockIdx.x * blockDim.x + threadIdx.x) * 4;
    if (i >= n) return;
    float4 v = *reinterpret_cast<const float4*>(in + i);
    *reinterpret_cast<__half2*>(out + i)     = __floats2half2_rn(v.x, v.y);
    *reinterpret_cast<__half2*>(out + i + 2) = __floats2half2_rn(v.z, v.w);
}

// ---------------- embedding + positional encoding (fp32 + fp16) -----------
__global__ void embed_pe_kernel(const int* __restrict__ ids,
                                const float* __restrict__ emb,
                                float* __restrict__ X,
                                __half* __restrict__ X16) {
    int idx = blockIdx.x * blockDim.x + threadIdx.x;
    if (idx >= NTOK * (DD / 2)) return;
    int row = idx >> 9;
    int p   = idx & 511;
    int s   = row & (SS - 1);
    int id  = ids[row];
    float freq = expf(-0.017988946039015358f * (float)p);  // 2*ln(1e4)/1024
    float sv, cv;
    sincosf((float)s * freq, &sv, &cv);
    size_t eo = (size_t)id * DD + 2 * p;
    size_t xo = (size_t)row * DD + 2 * p;
    float v0 = emb[eo] + sv, v1 = emb[eo + 1] + cv;
    X[xo] = v0; X[xo + 1] = v1;
    *reinterpret_cast<__half2*>(X16 + xo) = __floats2half2_rn(v0, v1);
}

// ---------------- fp16 tensor-core GEMM: C = A(MxK) * W(NxK)^T ------------
// BM=BN=128, BK=32, 128 threads (4 warps 2x2), warp tile 64x64, k16 MMA.
// 3-stage cp.async pipeline, dynamic smem (2 x 3 x 128 x 80B = 61.44 KB).
// Row stride 80B: LDSM 16B-chunk offsets mod 128 all distinct -> conflict-free.
#define GEMM_SMEM_BYTES (2 * 3 * 128 * 80)
#define G_STG (128 * 20)      // stage stride in u32 (10240 B)

template<int EPI, bool OUT16>   // EPI: 0 none, 1 +bias, 2 gelu(+bias)
__launch_bounds__(128, 2)
__global__ void gemm_f16_kernel(const __half* __restrict__ A,
                                const __half* __restrict__ W,
                                const float* __restrict__ bias,
                                float* __restrict__ Cf,
                                __half* __restrict__ Ch,
                                int M, int N, int K) {
    extern __shared__ __align__(16) uint32_t dynsm[];
    uint32_t* As = dynsm;                 // [3][128][20]
    uint32_t* Ws = dynsm + 3 * G_STG;     // [3][128][20]

    const int tid  = threadIdx.x;
    const int lane = tid & 31, warp = tid >> 5;
    const int wm = warp >> 1, wn = warp & 1;
    const int wrow = wm * 64, wcol = wn * 64;
    const int m0 = blockIdx.y * 128, n0 = blockIdx.x * 128;
    const int g = lane >> 2, tg = lane & 3;

    // ldmatrix lane-address bases (stage 0, tile 0, k-step 0)
    const int lrow = lane & 7, sel = lane >> 3;
    const uint32_t aAddr0 = smem_u32(As + (wrow + lrow + (sel & 1) * 8) * 20 + (sel >> 1) * 4);
    const uint32_t bAddr0 = smem_u32(Ws + (wcol + lrow + ((sel >> 1) & 1) * 8) * 20 + (sel & 1) * 4);
    const uint32_t stageB = G_STG * 4;    // 10240 bytes per stage

    auto issue = [&](int st, int k0) {
        int r = tid;   // one row each; 32 halfs = 64B = 4 cp16 per matrix
        const __half* a = A + (size_t)(m0 + r) * K + k0;
        const __half* w = W + (size_t)(n0 + r) * K + k0;
        uint32_t da = smem_u32(As + st * G_STG + r * 20);
        uint32_t dw = smem_u32(Ws + st * G_STG + r * 20);
        #pragma unroll
        for (int j = 0; j < 4; j++) {
            cp16(da + j * 16, a + j * 8);
            cp16(dw + j * 16, w + j * 8);
        }
    };

    float acc[4][8][4];
    #pragma unroll
    for (int mt = 0; mt < 4; mt++)
        #pragma unroll
        for (int nt = 0; nt < 8; nt++)
            #pragma unroll
            for (int r = 0; r < 4; r++) acc[mt][nt][r] = 0.f;

    const int nIter = K / 32;
    issue(0, 0);  cp_commit();
    issue(1, 32); cp_commit();

    for (int it = 0; it < nIter; it++) {
        if (it == nIter - 1) cp_wait<0>(); else cp_wait<1>();
        __syncthreads();
        if (it + 2 < nIter) { issue((it + 2) % 3, (it + 2) * 32); cp_commit(); }
        const int st = it % 3;
        const uint32_t aS = aAddr0 + st * stageB;
        const uint32_t bS = bAddr0 + st * stageB;

        #pragma unroll
        for (int ks = 0; ks < 2; ks++) {
            uint32_t af[4][4], bf[8][2];
            #pragma unroll
            for (int mt = 0; mt < 4; mt++)
                ldsm_x4(af[mt][0], af[mt][1], af[mt][2], af[mt][3],
                        aS + mt * 16 * 80 + ks * 32);
            #pragma unroll
            for (int ntp = 0; ntp < 4; ntp++)
                ldsm_x4(bf[2 * ntp][0], bf[2 * ntp][1], bf[2 * ntp + 1][0], bf[2 * ntp + 1][1],
                        bS + ntp * 16 * 80 + ks * 32);
            #pragma unroll
            for (int mt = 0; mt < 4; mt++)
                #pragma unroll
                for (int nt = 0; nt < 8; nt++)
                    mma_f16(acc[mt][nt], af[mt], bf[nt][0], bf[nt][1]);
        }
    }

    // epilogue
    #pragma unroll
    for (int mt = 0; mt < 4; mt++) {
        int r0 = m0 + wrow + mt * 16 + g;
        #pragma unroll
        for (int nt = 0; nt < 8; nt++) {
            int c = n0 + wcol + nt * 8 + 2 * tg;
            float b0 = 0.f, b1 = 0.f;
            if (EPI >= 1) { b0 = bias[c]; b1 = bias[c + 1]; }
            float v00 = acc[mt][nt][0] + b0, v01 = acc[mt][nt][1] + b1;
            float v10 = acc[mt][nt][2] + b0, v11 = acc[mt][nt][3] + b1;
            if (EPI == 2) {
                v00 = gelu_exact(v00); v01 = gelu_exact(v01);
                v10 = gelu_exact(v10); v11 = gelu_exact(v11);
            }
            if (OUT16) {
                *reinterpret_cast<__half2*>(Ch + (size_t)r0 * N + c)       = __floats2half2_rn(v00, v01);
                *reinterpret_cast<__half2*>(Ch + (size_t)(r0 + 8) * N + c) = __floats2half2_rn(v10, v11);
            } else {
                *reinterpret_cast<float2*>(Cf + (size_t)r0 * N + c)       = make_float2(v00, v01);
                *reinterpret_cast<float2*>(Cf + (size_t)(r0 + 8) * N + c) = make_float2(v10, v11);
            }
        }
    }
}

// ---------------- V transpose: qkv16 V-part -> Vt [b,h,dim,seq] -----------
__global__ void transpose_v_kernel(const __half* __restrict__ qkv16,
                                   __half* __restrict__ vt) {
    __shared__ __half t[32][33];
    int bh = blockIdx.z;
    int b = bh >> 4, h = bh & 15;
    int s0 = blockIdx.x * 32, d0 = blockIdx.y * 32;
    int tx = threadIdx.x, ty = threadIdx.y;   // 32 x 8
    #pragma unroll
    for (int i = 0; i < 4; i++) {
        int s = s0 + ty + i * 8;
        t[ty + i * 8][tx] = qkv16[((size_t)b * SS + s) * (3 * DD) + 2 * DD + h * HDIM + d0 + tx];
    }
    __syncthreads();
    #pragma unroll
    for (int i = 0; i < 4; i++) {
        int d = d0 + ty + i * 8;
        vt[((size_t)bh * HDIM + d) * SS + s0 + tx] = t[tx][ty + i * 8];
    }
}

// ---------------- fp16 flash attention, 128-query tiles, ldmatrix ---------
__launch_bounds__(128, 2)
__global__ void flash_f16_kernel(const __half* __restrict__ qkv16,
                                 const __half* __restrict__ vt,
                                 const int* __restrict__ mask,
                                 __half* __restrict__ out16) {
    __shared__ __align__(16) uint32_t Ks[3][32][36];   // keys x dim-u32 (144B rows); also Q staging
    __shared__ __align__(16) uint32_t Vst[3][64][20];  // dim x key-u32 (80B rows)
    __shared__ __align__(16) uint32_t Ps[128][20];     // q-rows x key-u32 fp16 (80B rows)
    __shared__ __align__(16) int msk[3][32];

    const int b = blockIdx.z, h_ = blockIdx.y;
    const int q0 = blockIdx.x * 128;
    const int tid = threadIdx.x, lane = tid & 31, warp = tid >> 5;
    const int g = lane >> 2, tg = lane & 3;
    const size_t base = (size_t)b * SS;
    const int qcol = h_ * HDIM;
    const size_t vtbase = ((size_t)(b * HH + h_)) * HDIM;

    const int lrow = lane & 7, sel = lane >> 3;
    const uint32_t kAddr0 = smem_u32(&Ks[0][lrow + ((sel >> 1) & 1) * 8][(sel & 1) * 4]);
    const uint32_t vAddr0 = smem_u32(&Vst[0][lrow + ((sel >> 1) & 1) * 8][(sel & 1) * 4]);
    const uint32_t pAddr0 = smem_u32(&Ps[lrow + (sel & 1) * 8][(sel >> 1) * 4]);
    const uint32_t kStage = 32 * 144, vStage = 64 * 80;

    // stage Q fp16 in two 64-row halves through the Ks region
    uint32_t* qst = &Ks[0][0][0];        // viewed as [64][36]
    uint32_t qf[2][4][4];
    #pragma unroll
    for (int half = 0; half < 2; half++) {
        #pragma unroll
        for (int i = 0; i < 4; i++) {
            int idx = tid + 128 * i;      // 512 16B-chunks = 64 rows x 8
            int r = idx >> 3, cj = idx & 7;
            uint4 v = *reinterpret_cast<const uint4*>(
                qkv16 + (base + q0 + half * 64 + r) * (3 * DD) + qcol + cj * 8);
            *reinterpret_cast<uint4*>(&qst[r * 36 + cj * 4]) = v;
        }
        __syncthreads();
        #pragma unroll
        for (int ks = 0; ks < 4; ks++) {
            int r = warp * 16 + g;
            qf[half][ks][0] = qst[r * 36 + ks * 8 + tg];
            qf[half][ks][1] = qst[(r + 8) * 36 + ks * 8 + tg];
            qf[half][ks][2] = qst[r * 36 + ks * 8 + tg + 4];
            qf[half][ks][3] = qst[(r + 8) * 36 + ks * 8 + tg + 4];
        }
        __syncthreads();
    }

    auto issueKV = [&](int st, int kc) {
        #pragma unroll
        for (int i = 0; i < 2; i++) {
            int e = tid + 128 * i;         // 0..255
            int r = e >> 3, cj = e & 7;
            cp16(smem_u32(&Ks[st][r][cj * 4]),
                 qkv16 + (base + kc + r) * (3 * DD) + DD + qcol + cj * 8);
        }
        #pragma unroll
        for (int i = 0; i < 2; i++) {
            int e = tid + 128 * i;         // 0..255
            int r = e >> 2, cj = e & 3;
            cp16(smem_u32(&Vst[st][r][cj * 4]),
                 vt + (vtbase + r) * SS + kc + cj * 8);
        }
        if (tid < 8) cp16(smem_u32(&msk[st][tid * 4]), mask + b * SS + kc + tid * 4);
    };

    float o[2][8][4];
    #pragma unroll
    for (int h = 0; h < 2; h++)
        #pragma unroll
        for (int nt = 0; nt < 8; nt++)
            #pragma unroll
            for (int r = 0; r < 4; r++) o[h][nt][r] = 0.f;
    float mprev[2][2] = {{-1e30f, -1e30f}, {-1e30f, -1e30f}};
    float lsum[2][2]  = {{0.f, 0.f}, {0.f, 0.f}};

    const int nIter = SS / 32;   // 64
    issueKV(0, 0);  cp_commit();
    issueKV(1, 32); cp_commit();

    for (int it = 0; it < nIter; it++) {
        if (it == nIter - 1) cp_wait<0>(); else cp_wait<1>();
        __syncthreads();
        if (it + 2 < nIter) { issueKV((it + 2) % 3, (it + 2) * 32); cp_commit(); }
        const int st = it % 3;
        const uint32_t kS = kAddr0 + st * kStage;
        const uint32_t vS = vAddr0 + st * vStage;

        // S = Q K^T (4 k16 steps over 64 dims)
        float s[2][4][4];
        #pragma unroll
        for (int h = 0; h < 2; h++)
            #pragma unroll
            for (int nt = 0; nt < 4; nt++)
                #pragma unroll
                for (int r = 0; r < 4; r++) s[h][nt][r] = 0.f;
        #pragma unroll
        for (int ks = 0; ks < 4; ks++) {
            uint32_t kb[4][2];
            ldsm_x4(kb[0][0], kb[0][1], kb[1][0], kb[1][1], kS + ks * 32);
            ldsm_x4(kb[2][0], kb[2][1], kb[3][0], kb[3][1], kS + 16 * 144 + ks * 32);
            #pragma unroll
            for (int h = 0; h < 2; h++)
                #pragma unroll
                for (int nt = 0; nt < 4; nt++)
                    mma_f16(s[h][nt], qf[h][ks], kb[nt][0], kb[nt][1]);
        }

        // scale + mask + online softmax per half
        float alpha[2][2];
        #pragma unroll
        for (int h = 0; h < 2; h++) {
            float mx0 = -1e30f, mx1 = -1e30f;
            #pragma unroll
            for (int nt = 0; nt < 4; nt++) {
                int c = nt * 8 + 2 * tg;
                s[h][nt][0] *= 0.125f; s[h][nt][1] *= 0.125f;
                s[h][nt][2] *= 0.125f; s[h][nt][3] *= 0.125f;
                if (msk[st][c] == 0)     { s[h][nt][0] = -1e30f; s[h][nt][2] = -1e30f; }
                if (msk[st][c + 1] == 0) { s[h][nt][1] = -1e30f; s[h][nt][3] = -1e30f; }
                mx0 = fmaxf(mx0, fmaxf(s[h][nt][0], s[h][nt][1]));
                mx1 = fmaxf(mx1, fmaxf(s[h][nt][2], s[h][nt][3]));
            }
            mx0 = fmaxf(mx0, __shfl_xor_sync(0xffffffffu, mx0, 1));
            mx0 = fmaxf(mx0, __shfl_xor_sync(0xffffffffu, mx0, 2));
            mx1 = fmaxf(mx1, __shfl_xor_sync(0xffffffffu, mx1, 1));
            mx1 = fmaxf(mx1, __shfl_xor_sync(0xffffffffu, mx1, 2));

            float mn0 = fmaxf(mprev[h][0], mx0), mn1 = fmaxf(mprev[h][1], mx1);
            alpha[h][0] = __expf(mprev[h][0] - mn0);
            alpha[h][1] = __expf(mprev[h][1] - mn1);

            float ps0 = 0.f, ps1 = 0.f;
            #pragma unroll
            for (int nt = 0; nt < 4; nt++) {
                float e00 = __expf(s[h][nt][0] - mn0);
                float e01 = __expf(s[h][nt][1] - mn0);
                float e10 = __expf(s[h][nt][2] - mn1);
                float e11 = __expf(s[h][nt][3] - mn1);
                ps0 += e00 + e01;
                ps1 += e10 + e11;
                int r = h * 64 + warp * 16 + g;
                Ps[r][nt * 4 + tg]     = pack_half2(e00, e01);
                Ps[r + 8][nt * 4 + tg] = pack_half2(e10, e11);
            }
            lsum[h][0] = lsum[h][0] * alpha[h][0] + ps0;
            lsum[h][1] = lsum[h][1] * alpha[h][1] + ps1;
            mprev[h][0] = mn0; mprev[h][1] = mn1;
        }
        __syncwarp();   // P writes visible before ldmatrix reads (warp-local rows)

        // O *= alpha — skipped entirely when every lane's alpha is exactly 1
        // (exp(0) == 1.0f exact; max unchanged for most chunks)
        bool need = (alpha[0][0] != 1.f) | (alpha[0][1] != 1.f) |
                    (alpha[1][0] != 1.f) | (alpha[1][1] != 1.f);
        if (__any_sync(0xffffffffu, need)) {
            #pragma unroll
            for (int h = 0; h < 2; h++)
                #pragma unroll
                for (int nt = 0; nt < 8; nt++) {
                    o[h][nt][0] *= alpha[h][0]; o[h][nt][1] *= alpha[h][0];
                    o[h][nt][2] *= alpha[h][1]; o[h][nt][3] *= alpha[h][1];
                }
        }
        // O += P V  (2 k16 steps over 32 keys)
        #pragma unroll
        for (int ks = 0; ks < 2; ks++) {
            uint32_t vb[8][2];
            #pragma unroll
            for (int ntp = 0; ntp < 4; ntp++)
                ldsm_x4(vb[2 * ntp][0], vb[2 * ntp][1], vb[2 * ntp + 1][0], vb[2 * ntp + 1][1],
                        vS + ntp * 16 * 80 + ks * 32);
            #pragma unroll
            for (int h = 0; h < 2; h++) {
                uint32_t af[4];
                ldsm_x4(af[0], af[1], af[2], af[3],
                        pAddr0 + (h * 64 + warp * 16) * 80 + ks * 32);
                #pragma unroll
                for (int nt = 0; nt < 8; nt++)
                    mma_f16(o[h][nt], af, vb[nt][0], vb[nt][1]);
            }
        }
        __syncwarp();
    }

    #pragma unroll
    for (int h = 0; h < 2; h++) {
        float l0 = lsum[h][0], l1 = lsum[h][1];
        l0 += __shfl_xor_sync(0xffffffffu, l0, 1);
        l0 += __shfl_xor_sync(0xffffffffu, l0, 2);
        l1 += __shfl_xor_sync(0xffffffffu, l1, 1);
        l1 += __shfl_xor_sync(0xffffffffu, l1, 2);
        float inv0 = 1.0f / l0, inv1 = 1.0f / l1;

        int r0 = q0 + h * 64 + warp * 16 + g;
        #pragma unroll
        for (int nt = 0; nt < 8; nt++) {
            int c = qcol + nt * 8 + 2 * tg;
            *reinterpret_cast<__half2*>(out16 + (base + r0) * DD + c) =
                __floats2half2_rn(o[h][nt][0] * inv0, o[h][nt][1] * inv0);
            *reinterpret_cast<__half2*>(out16 + (base + r0 + 8) * DD + c) =
                __floats2half2_rn(o[h][nt][2] * inv1, o[h][nt][3] * inv1);
        }
    }
}

// ---------------- residual add + LayerNorm (fp32 + optional fp16 out) -----
__device__ __forceinline__ float block_reduce_256(float v, float* red) {
    __syncthreads();
    int t = threadIdx.x;
    #pragma unroll
    for (int o = 16; o > 0; o >>= 1) v += __shfl_down_sync(0xffffffffu, v, o);
    if ((t & 31) == 0) red[t >> 5] = v;
    __syncthreads();
    if (t < 8) {
        v = red[t];
        #pragma unroll
        for (int o = 4; o > 0; o >>= 1) v += __shfl_down_sync(0xffu, v, o);
        if (t == 0) red[0] = v;
    }
    __syncthreads();
    return red[0];
}

template<bool OUT16>
__global__ void add_ln_kernel(const float* __restrict__ A,
                              float* __restrict__ X,
                              __half* __restrict__ X16,
                              const float* __restrict__ g,
                              const float* __restrict__ bt) {
    __shared__ float red[32];
    int r = blockIdx.x, t = threadIdx.x;
    const float* a = A + (size_t)r * DD;
    float* x = X + (size_t)r * DD;
    int d0 = t * 4;
    float4 av = *reinterpret_cast<const float4*>(a + d0);
    float4 xv = *reinterpret_cast<const float4*>(x + d0);
    float v[4] = {av.x + xv.x, av.y + xv.y, av.z + xv.z, av.w + xv.w};
    float sum = v[0] + v[1] + v[2] + v[3];
    sum = block_reduce_256(sum, red);
    float mu = sum * (1.0f / DD);
    float vs = 0.f;
    #pragma unroll
    for (int i = 0; i < 4; i++) { float dl = v[i] - mu; vs += dl * dl; }
    vs = block_reduce_256(vs, red);
    float rs = rsqrtf(vs * (1.0f / DD) + 1e-5f);
    float o[4];
    #pragma unroll
    for (int i = 0; i < 4; i++)
        o[i] = (v[i] - mu) * rs * g[d0 + i] + bt[d0 + i];
    *reinterpret_cast<float4*>(x + d0) = make_float4(o[0], o[1], o[2], o[3]);
    if (OUT16) {
        __half* x16 = X16 + (size_t)r * DD + d0;
        *reinterpret_cast<__half2*>(x16)     = __floats2half2_rn(o[0], o[1]);
        *reinterpret_cast<__half2*>(x16 + 2) = __floats2half2_rn(o[2], o[3]);
    }
}

// ---------------- masked max-pool over sequence ----------------
__global__ void pool_partial_kernel(const float* __restrict__ X,
                                    const int* __restrict__ mask,
                                    float* __restrict__ part) {
    int b = blockIdx.y, ch = blockIdx.x;
    int d = threadIdx.x;
    float m = -INFINITY;
    for (int s = 0; s < 128; s++) {
        int srow = ch * 128 + s;
        float val = X[((size_t)b * SS + srow) * DD + d];
        if (mask[b * SS + srow] != 0) m = fmaxf(m, val);
    }
    part[((size_t)b * 16 + ch) * DD + d] = m;
}

__global__ void pool_final_kernel(const float* __restrict__ part,
                                  float* __restrict__ pooled) {
    int b = blockIdx.x, d = threadIdx.x;
    float m = -INFINITY;
    for (int c = 0; c < 16; c++)
        m = fmaxf(m, part[((size_t)b * 16 + c) * DD + d]);
    pooled[b * DD + d] = m;
}

// ---------------- small head FC ----------------
__global__ void head_fc_kernel(const float* __restrict__ in,
                               const float* __restrict__ W,
                               const float* __restrict__ bias,
                               float* __restrict__ out,
                               int K, int apply_gelu) {
    __shared__ float red[4];
    int n = blockIdx.x, b = blockIdx.y, t = threadIdx.x;
    int N = gridDim.x;
    const float* ip = in + (size_t)b * K;
    const float* wp = W + (size_t)n * K;
    float s = 0.f;
    for (int k = t; k < K; k += 128) s += ip[k] * wp[k];
    #pragma unroll
    for (int o = 16; o > 0; o >>= 1) s += __shfl_down_sync(0xffffffffu, s, o);
    if ((t & 31) == 0) red[t >> 5] = s;
    __syncthreads();
    if (t == 0) {
        float v = red[0] + red[1] + red[2] + red[3] + bias[n];
        if (apply_gelu) v = gelu_exact(v);
        out[b * N + n] = v;
    }
}

// ---------------- launch ----------------
extern "C" void kernel_launch(void* const* d_in, const int* in_sizes, int n_in,
                              void* d_out, int out_size) {
    const int*   x_ids  = (const int*)d_in[0];
    const int*   mask   = (const int*)d_in[1];
    const float* emb    = (const float*)d_in[2];
    const float* qkv_w  = (const float*)d_in[3];
    const float* fc_w   = (const float*)d_in[4];
    const float* fc_b   = (const float*)d_in[5];
    const float* ln1_g  = (const float*)d_in[6];
    const float* ln1_b  = (const float*)d_in[7];
    const float* ffn_w1 = (const float*)d_in[8];
    const float* ffn_b1 = (const float*)d_in[9];
    const float* ffn_w2 = (const float*)d_in[10];
    const float* ffn_b2 = (const float*)d_in[11];
    const float* ln2_g  = (const float*)d_in[12];
    const float* ln2_b  = (const float*)d_in[13];
    const float* pr_w1  = (const float*)d_in[14];
    const float* pr_b1  = (const float*)d_in[15];
    const float* pr_w2  = (const float*)d_in[16];
    const float* pr_b2  = (const float*)d_in[17];
    float* out = (float*)d_out;

    float *X, *O, *part, *pool, *hh;
    __half *X16, *QKV16, *Vt16, *AO16, *H16, *Wq16, *Wf16, *W116, *W216;
    cudaGetSymbolAddress((void**)&X,     g_X);
    cudaGetSymbolAddress((void**)&O,     g_O);
    cudaGetSymbolAddress((void**)&X16,   g_X16);
    cudaGetSymbolAddress((void**)&QKV16, g_QKV16);
    cudaGetSymbolAddress((void**)&Vt16,  g_Vt16);
    cudaGetSymbolAddress((void**)&AO16,  g_AO16);
    cudaGetSymbolAddress((void**)&H16,   g_H16);
    cudaGetSymbolAddress((void**)&Wq16,  g_Wq16);
    cudaGetSymbolAddress((void**)&Wf16,  g_Wf16);
    cudaGetSymbolAddress((void**)&W116,  g_W116);
    cudaGetSymbolAddress((void**)&W216,  g_W216);
    cudaGetSymbolAddress((void**)&part,  g_part);
    cudaGetSymbolAddress((void**)&pool,  g_pool);
    cudaGetSymbolAddress((void**)&hh,    g_hh);

    static bool attr_done = false;
    if (!attr_done) {
        cudaFuncSetAttribute(gemm_f16_kernel<0, true>,
            cudaFuncAttributeMaxDynamicSharedMemorySize, GEMM_SMEM_BYTES);
        cudaFuncSetAttribute(gemm_f16_kernel<1, false>,
            cudaFuncAttributeMaxDynamicSharedMemorySize, GEMM_SMEM_BYTES);
        cudaFuncSetAttribute(gemm_f16_kernel<2, true>,
            cudaFuncAttributeMaxDynamicSharedMemorySize, GEMM_SMEM_BYTES);
        attr_done = true;
    }

    // 0. convert weights to fp16
    f2h_kernel<<<(3 * DD * DD / 4 + 255) / 256, 256>>>(qkv_w,  Wq16, 3 * DD * DD);
    f2h_kernel<<<(DD * DD / 4 + 255) / 256, 256>>>(fc_w,   Wf16, DD * DD);
    f2h_kernel<<<(FFN * DD / 4 + 255) / 256, 256>>>(ffn_w1, W116, FFN * DD);
    f2h_kernel<<<(DD * FFN / 4 + 255) / 256, 256>>>(ffn_w2, W216, DD * FFN);

    // 1. embedding + positional encoding (fp32 + fp16)
    embed_pe_kernel<<<(NTOK * (DD / 2)) / 256, 256>>>(x_ids, emb, X, X16);

    // 2. QKV projection -> fp16
    gemm_f16_kernel<0, true><<<dim3(3 * DD / 128, NTOK / 128), 128, GEMM_SMEM_BYTES>>>(
        X16, Wq16, nullptr, nullptr, QKV16, NTOK, 3 * DD, DD);

    // 2b. transpose V
    transpose_v_kernel<<<dim3(SS / 32, HDIM / 32, BB * HH), dim3(32, 8)>>>(QKV16, Vt16);

    // 3. attention (fp16 MMA + ldmatrix)
    flash_f16_kernel<<<dim3(SS / 128, HH, BB), 128>>>(QKV16, Vt16, mask, AO16);

    // 4. output projection (+bias) -> fp32
    gemm_f16_kernel<1, false><<<dim3(DD / 128, NTOK / 128), 128, GEMM_SMEM_BYTES>>>(
        AO16, Wf16, fc_b, O, nullptr, NTOK, DD, DD);

    // 5. residual + LN1 (fp32 X + fp16 copy)
    add_ln_kernel<true><<<NTOK, 256>>>(O, X, X16, ln1_g, ln1_b);

    // 6. FFN up (+bias, gelu) -> fp16
    gemm_f16_kernel<2, true><<<dim3(FFN / 128, NTOK / 128), 128, GEMM_SMEM_BYTES>>>(
        X16, W116, ffn_b1, nullptr, H16, NTOK, FFN, DD);

    // 7. FFN down (+bias) -> fp32
    gemm_f16_kernel<1, false><<<dim3(DD / 128, NTOK / 128), 128, GEMM_SMEM_BYTES>>>(
        H16, W216, ffn_b2, O, nullptr, NTOK, DD, FFN);

    // 8. residual + LN2 (fp32 only)
    add_ln_kernel<false><<<NTOK, 256>>>(O, X, nullptr, ln2_g, ln2_b);

    // 9. masked max-pool
    pool_partial_kernel<<<dim3(16, BB), 1024>>>(X, mask, part);
    pool_final_kernel<<<BB, 1024>>>(part, pool);

    // 10. prediction head
    head_fc_kernel<<<dim3(DD, BB), 128>>>(pool, pr_w1, pr_b1, hh, DD, 1);
    head_fc_kernel<<<dim3(10, BB), 128>>>(hh, pr_w2, pr_b2, out, DD, 0);
}

// round 15
// speedup vs baseline: 1.0845x; 1.0845x over previous
#include <cuda_runtime.h>
#include <cuda_fp16.h>
#include <math.h>
#include <stdint.h>

// Problem constants
#define BB 4
#define SS 2048
#define DD 1024
#define HH 16
#define HDIM 64
#define FFN 2048
#define NTOK (BB*SS)          // 8192

// ---------------- scratch (device globals: allocation-free) ----------------
__device__ float  g_X   [NTOK * DD];          // fp32 residual stream
__device__ float  g_O   [NTOK * DD];          // fp32 gemm output
__device__ __half g_X16 [NTOK * DD];          // fp16 activation copy
__device__ __half g_QKV16[NTOK * 3 * DD];
__device__ __half g_Vt16 [BB * HH * HDIM * SS];  // V transposed [b,h,dim,seq]
__device__ __half g_AO16 [NTOK * DD];
__device__ __half g_H16  [NTOK * FFN];
__device__ __half g_Wq16 [3 * DD * DD];
__device__ __half g_Wf16 [DD * DD];
__device__ __half g_W116 [FFN * DD];
__device__ __half g_W216 [DD * FFN];
__device__ float  g_part[BB * 16 * DD];
__device__ float  g_pool[BB * DD];
__device__ float  g_hh  [BB * DD];

__device__ __forceinline__ float gelu_exact(float v) {
    return 0.5f * v * (1.0f + erff(v * 0.7071067811865476f));
}

__device__ __forceinline__ uint32_t smem_u32(const void* p) {
    return (uint32_t)__cvta_generic_to_shared(p);
}
__device__ __forceinline__ void cp16(uint32_t dst, const void* src) {
    asm volatile("cp.async.cg.shared.global [%0], [%1], 16;" :: "r"(dst), "l"(src));
}
__device__ __forceinline__ void cp_commit() {
    asm volatile("cp.async.commit_group;");
}
template<int N>
__device__ __forceinline__ void cp_wait() {
    asm volatile("cp.async.wait_group %0;" :: "n"(N));
}

// fp16 MMA, fp32 accumulate: m16n8k16
__device__ __forceinline__ void mma_f16(float* d, const uint32_t* a, uint32_t b0, uint32_t b1) {
    asm volatile(
        "mma.sync.aligned.m16n8k16.row.col.f32.f16.f16.f32 "
        "{%0,%1,%2,%3}, {%4,%5,%6,%7}, {%8,%9}, {%0,%1,%2,%3};\n"
        : "+f"(d[0]), "+f"(d[1]), "+f"(d[2]), "+f"(d[3])
        : "r"(a[0]), "r"(a[1]), "r"(a[2]), "r"(a[3]), "r"(b0), "r"(b1));
}

// non-trans ldmatrix x4: A-type ([m][k] rows) and B-type stored as [n][k] rows
__device__ __forceinline__ void ldsm_x4(uint32_t& r0, uint32_t& r1, uint32_t& r2, uint32_t& r3,
                                        uint32_t addr) {
    asm volatile("ldmatrix.sync.aligned.m8n8.x4.shared.b16 {%0,%1,%2,%3}, [%4];"
                 : "=r"(r0), "=r"(r1), "=r"(r2), "=r"(r3) : "r"(addr));
}

__device__ __forceinline__ uint32_t pack_half2(float a, float b) {
    __half2 h = __floats2half2_rn(a, b);
    uint32_t u;
    memcpy(&u, &h, 4);
    return u;
}

// ---------------- fp32 -> fp16 weight conversion ----------------
__global__ void f2h_kernel(const float* __restrict__ in, __half* __restrict__ out, int n) {
    int i = (blockIdx.x * blockDim.x + threadIdx.x) * 4;
    if (i >= n) return;
    float4 v = *reinterpret_cast<const float4*>(in + i);
    *reinterpret_cast<__half2*>(out + i)     = __floats2half2_rn(v.x, v.y);
    *reinterpret_cast<__half2*>(out + i + 2) = __floats2half2_rn(v.z, v.w);
}

// ---------------- embedding + positional encoding (fp32 + fp16) -----------
__global__ void embed_pe_kernel(const int* __restrict__ ids,
                                const float* __restrict__ emb,
                                float* __restrict__ X,
                                __half* __restrict__ X16) {
    int idx = blockIdx.x * blockDim.x + threadIdx.x;
    if (idx >= NTOK * (DD / 2)) return;
    int row = idx >> 9;
    int p   = idx & 511;
    int s   = row & (SS - 1);
    int id  = ids[row];
    float freq = expf(-0.017988946039015358f * (float)p);  // 2*ln(1e4)/1024
    float sv, cv;
    sincosf((float)s * freq, &sv, &cv);
    size_t eo = (size_t)id * DD + 2 * p;
    size_t xo = (size_t)row * DD + 2 * p;
    float v0 = emb[eo] + sv, v1 = emb[eo + 1] + cv;
    X[xo] = v0; X[xo + 1] = v1;
    *reinterpret_cast<__half2*>(X16 + xo) = __floats2half2_rn(v0, v1);
}

// ---------------- fp16 tensor-core GEMM: C = A(MxK) * W(NxK)^T ------------
// BM=BN=128, BK=16, 128 threads (4 warps 2x2), warp tile 64x64, k16 MMA.
// ldmatrix fragment loads: 4 x4 (A) + 4 x4 (B, [n][k] rows) per iter.
// (R13-proven configuration: static smem, 3-stage, wait<1>.)
template<int EPI, bool OUT16>   // EPI: 0 none, 1 +bias, 2 gelu(+bias)
__launch_bounds__(128, 2)
__global__ void gemm_f16_kernel(const __half* __restrict__ A,
                                const __half* __restrict__ W,
                                const float* __restrict__ bias,
                                float* __restrict__ Cf,
                                __half* __restrict__ Ch,
                                int M, int N, int K) {
    __shared__ __align__(16) uint32_t As[3][128][12];   // 8 u32 used, row stride 48B
    __shared__ __align__(16) uint32_t Ws[3][128][12];

    const int tid  = threadIdx.x;
    const int lane = tid & 31, warp = tid >> 5;
    const int wm = warp >> 1, wn = warp & 1;
    const int wrow = wm * 64, wcol = wn * 64;
    const int m0 = blockIdx.y * 128, n0 = blockIdx.x * 128;
    const int g = lane >> 2, tg = lane & 3;

    // ldmatrix lane-address bases (stage 0, tile 0)
    const int lrow = lane & 7, sel = lane >> 3;
    const uint32_t aAddr0 = smem_u32(&As[0][wrow + lrow + (sel & 1) * 8][(sel >> 1) * 4]);
    const uint32_t bAddr0 = smem_u32(&Ws[0][wcol + lrow + ((sel >> 1) & 1) * 8][(sel & 1) * 4]);
    const uint32_t stageB = 128 * 48;    // 6144 bytes per stage

    auto issue = [&](int st, int k0) {
        int r = tid;   // 0..127, one row each
        const __half* a = A + (size_t)(m0 + r) * K + k0;
        cp16(smem_u32(&As[st][r][0]), a);
        cp16(smem_u32(&As[st][r][4]), a + 8);
        const __half* w = W + (size_t)(n0 + r) * K + k0;
        cp16(smem_u32(&Ws[st][r][0]), w);
        cp16(smem_u32(&Ws[st][r][4]), w + 8);
    };

    float acc[4][8][4];
    #pragma unroll
    for (int mt = 0; mt < 4; mt++)
        #pragma unroll
        for (int nt = 0; nt < 8; nt++)
            #pragma unroll
            for (int r = 0; r < 4; r++) acc[mt][nt][r] = 0.f;

    const int nIter = K / 16;
    issue(0, 0);  cp_commit();
    issue(1, 16); cp_commit();

    for (int it = 0; it < nIter; it++) {
        if (it == nIter - 1) cp_wait<0>(); else cp_wait<1>();
        __syncthreads();
        if (it + 2 < nIter) { issue((it + 2) % 3, (it + 2) * 16); cp_commit(); }
        const int st = it % 3;
        const uint32_t aS = aAddr0 + st * stageB;
        const uint32_t bS = bAddr0 + st * stageB;

        uint32_t af[4][4], bf[8][2];
        #pragma unroll
        for (int mt = 0; mt < 4; mt++)
            ldsm_x4(af[mt][0], af[mt][1], af[mt][2], af[mt][3], aS + mt * 16 * 48);
        #pragma unroll
        for (int ntp = 0; ntp < 4; ntp++)
            ldsm_x4(bf[2 * ntp][0], bf[2 * ntp][1], bf[2 * ntp + 1][0], bf[2 * ntp + 1][1],
                    bS + ntp * 16 * 48);
        #pragma unroll
        for (int mt = 0; mt < 4; mt++)
            #pragma unroll
            for (int nt = 0; nt < 8; nt++)
                mma_f16(acc[mt][nt], af[mt], bf[nt][0], bf[nt][1]);
    }

    // epilogue
    #pragma unroll
    for (int mt = 0; mt < 4; mt++) {
        int r0 = m0 + wrow + mt * 16 + g;
        #pragma unroll
        for (int nt = 0; nt < 8; nt++) {
            int c = n0 + wcol + nt * 8 + 2 * tg;
            float b0 = 0.f, b1 = 0.f;
            if (EPI >= 1) { b0 = bias[c]; b1 = bias[c + 1]; }
            float v00 = acc[mt][nt][0] + b0, v01 = acc[mt][nt][1] + b1;
            float v10 = acc[mt][nt][2] + b0, v11 = acc[mt][nt][3] + b1;
            if (EPI == 2) {
                v00 = gelu_exact(v00); v01 = gelu_exact(v01);
                v10 = gelu_exact(v10); v11 = gelu_exact(v11);
            }
            if (OUT16) {
                *reinterpret_cast<__half2*>(Ch + (size_t)r0 * N + c)       = __floats2half2_rn(v00, v01);
                *reinterpret_cast<__half2*>(Ch + (size_t)(r0 + 8) * N + c) = __floats2half2_rn(v10, v11);
            } else {
                *reinterpret_cast<float2*>(Cf + (size_t)r0 * N + c)       = make_float2(v00, v01);
                *reinterpret_cast<float2*>(Cf + (size_t)(r0 + 8) * N + c) = make_float2(v10, v11);
            }
        }
    }
}

// ---------------- V transpose: qkv16 V-part -> Vt [b,h,dim,seq] -----------
__global__ void transpose_v_kernel(const __half* __restrict__ qkv16,
                                   __half* __restrict__ vt) {
    __shared__ __half t[32][33];
    int bh = blockIdx.z;
    int b = bh >> 4, h = bh & 15;
    int s0 = blockIdx.x * 32, d0 = blockIdx.y * 32;
    int tx = threadIdx.x, ty = threadIdx.y;   // 32 x 8
    #pragma unroll
    for (int i = 0; i < 4; i++) {
        int s = s0 + ty + i * 8;
        t[ty + i * 8][tx] = qkv16[((size_t)b * SS + s) * (3 * DD) + 2 * DD + h * HDIM + d0 + tx];
    }
    __syncthreads();
    #pragma unroll
    for (int i = 0; i < 4; i++) {
        int d = d0 + ty + i * 8;
        vt[((size_t)bh * HDIM + d) * SS + s0 + tx] = t[tx][ty + i * 8];
    }
}

// ---------------- fp16 flash attention, 128-query tiles, ldmatrix ---------
__launch_bounds__(128, 2)
__global__ void flash_f16_kernel(const __half* __restrict__ qkv16,
                                 const __half* __restrict__ vt,
                                 const int* __restrict__ mask,
                                 __half* __restrict__ out16) {
    __shared__ __align__(16) uint32_t Ks[3][32][36];   // keys x dim-u32 (144B rows); also Q staging
    __shared__ __align__(16) uint32_t Vst[3][64][20];  // dim x key-u32 (80B rows)
    __shared__ __align__(16) uint32_t Ps[128][20];     // q-rows x key-u32 fp16 (80B rows)
    __shared__ __align__(16) int msk[3][32];

    const int b = blockIdx.z, h_ = blockIdx.y;
    const int q0 = blockIdx.x * 128;
    const int tid = threadIdx.x, lane = tid & 31, warp = tid >> 5;
    const int g = lane >> 2, tg = lane & 3;
    const size_t base = (size_t)b * SS;
    const int qcol = h_ * HDIM;
    const size_t vtbase = ((size_t)(b * HH + h_)) * HDIM;

    const int lrow = lane & 7, sel = lane >> 3;
    const uint32_t kAddr0 = smem_u32(&Ks[0][lrow + ((sel >> 1) & 1) * 8][(sel & 1) * 4]);
    const uint32_t vAddr0 = smem_u32(&Vst[0][lrow + ((sel >> 1) & 1) * 8][(sel & 1) * 4]);
    const uint32_t pAddr0 = smem_u32(&Ps[lrow + (sel & 1) * 8][(sel >> 1) * 4]);
    const uint32_t kStage = 32 * 144, vStage = 64 * 80;

    // stage Q fp16 in two 64-row halves through the Ks region
    uint32_t* qst = &Ks[0][0][0];        // viewed as [64][36]
    uint32_t qf[2][4][4];
    #pragma unroll
    for (int half = 0; half < 2; half++) {
        #pragma unroll
        for (int i = 0; i < 4; i++) {
            int idx = tid + 128 * i;      // 512 16B-chunks = 64 rows x 8
            int r = idx >> 3, cj = idx & 7;
            uint4 v = *reinterpret_cast<const uint4*>(
                qkv16 + (base + q0 + half * 64 + r) * (3 * DD) + qcol + cj * 8);
            *reinterpret_cast<uint4*>(&qst[r * 36 + cj * 4]) = v;
        }
        __syncthreads();
        #pragma unroll
        for (int ks = 0; ks < 4; ks++) {
            int r = warp * 16 + g;
            qf[half][ks][0] = qst[r * 36 + ks * 8 + tg];
            qf[half][ks][1] = qst[(r + 8) * 36 + ks * 8 + tg];
            qf[half][ks][2] = qst[r * 36 + ks * 8 + tg + 4];
            qf[half][ks][3] = qst[(r + 8) * 36 + ks * 8 + tg + 4];
        }
        __syncthreads();
    }

    auto issueKV = [&](int st, int kc) {
        #pragma unroll
        for (int i = 0; i < 2; i++) {
            int e = tid + 128 * i;         // 0..255
            int r = e >> 3, cj = e & 7;
            cp16(smem_u32(&Ks[st][r][cj * 4]),
                 qkv16 + (base + kc + r) * (3 * DD) + DD + qcol + cj * 8);
        }
        #pragma unroll
        for (int i = 0; i < 2; i++) {
            int e = tid + 128 * i;         // 0..255
            int r = e >> 2, cj = e & 3;
            cp16(smem_u32(&Vst[st][r][cj * 4]),
                 vt + (vtbase + r) * SS + kc + cj * 8);
        }
        if (tid < 8) cp16(smem_u32(&msk[st][tid * 4]), mask + b * SS + kc + tid * 4);
    };

    float o[2][8][4];
    #pragma unroll
    for (int h = 0; h < 2; h++)
        #pragma unroll
        for (int nt = 0; nt < 8; nt++)
            #pragma unroll
            for (int r = 0; r < 4; r++) o[h][nt][r] = 0.f;
    float mprev[2][2] = {{-1e30f, -1e30f}, {-1e30f, -1e30f}};
    float lsum[2][2]  = {{0.f, 0.f}, {0.f, 0.f}};

    const int nIter = SS / 32;   // 64
    issueKV(0, 0);  cp_commit();
    issueKV(1, 32); cp_commit();

    for (int it = 0; it < nIter; it++) {
        if (it == nIter - 1) cp_wait<0>(); else cp_wait<1>();
        __syncthreads();
        if (it + 2 < nIter) { issueKV((it + 2) % 3, (it + 2) * 32); cp_commit(); }
        const int st = it % 3;
        const uint32_t kS = kAddr0 + st * kStage;
        const uint32_t vS = vAddr0 + st * vStage;

        // S = Q K^T (4 k16 steps over 64 dims)
        float s[2][4][4];
        #pragma unroll
        for (int h = 0; h < 2; h++)
            #pragma unroll
            for (int nt = 0; nt < 4; nt++)
                #pragma unroll
                for (int r = 0; r < 4; r++) s[h][nt][r] = 0.f;
        #pragma unroll
        for (int ks = 0; ks < 4; ks++) {
            uint32_t kb[4][2];
            ldsm_x4(kb[0][0], kb[0][1], kb[1][0], kb[1][1], kS + ks * 32);
            ldsm_x4(kb[2][0], kb[2][1], kb[3][0], kb[3][1], kS + 16 * 144 + ks * 32);
            #pragma unroll
            for (int h = 0; h < 2; h++)
                #pragma unroll
                for (int nt = 0; nt < 4; nt++)
                    mma_f16(s[h][nt], qf[h][ks], kb[nt][0], kb[nt][1]);
        }

        // scale + mask + online softmax per half
        float alpha[2][2];
        #pragma unroll
        for (int h = 0; h < 2; h++) {
            float mx0 = -1e30f, mx1 = -1e30f;
            #pragma unroll
            for (int nt = 0; nt < 4; nt++) {
                int c = nt * 8 + 2 * tg;
                s[h][nt][0] *= 0.125f; s[h][nt][1] *= 0.125f;
                s[h][nt][2] *= 0.125f; s[h][nt][3] *= 0.125f;
                if (msk[st][c] == 0)     { s[h][nt][0] = -1e30f; s[h][nt][2] = -1e30f; }
                if (msk[st][c + 1] == 0) { s[h][nt][1] = -1e30f; s[h][nt][3] = -1e30f; }
                mx0 = fmaxf(mx0, fmaxf(s[h][nt][0], s[h][nt][1]));
                mx1 = fmaxf(mx1, fmaxf(s[h][nt][2], s[h][nt][3]));
            }
            mx0 = fmaxf(mx0, __shfl_xor_sync(0xffffffffu, mx0, 1));
            mx0 = fmaxf(mx0, __shfl_xor_sync(0xffffffffu, mx0, 2));
            mx1 = fmaxf(mx1, __shfl_xor_sync(0xffffffffu, mx1, 1));
            mx1 = fmaxf(mx1, __shfl_xor_sync(0xffffffffu, mx1, 2));

            float mn0 = fmaxf(mprev[h][0], mx0), mn1 = fmaxf(mprev[h][1], mx1);
            alpha[h][0] = __expf(mprev[h][0] - mn0);
            alpha[h][1] = __expf(mprev[h][1] - mn1);

            float ps0 = 0.f, ps1 = 0.f;
            #pragma unroll
            for (int nt = 0; nt < 4; nt++) {
                float e00 = __expf(s[h][nt][0] - mn0);
                float e01 = __expf(s[h][nt][1] - mn0);
                float e10 = __expf(s[h][nt][2] - mn1);
                float e11 = __expf(s[h][nt][3] - mn1);
                ps0 += e00 + e01;
                ps1 += e10 + e11;
                int r = h * 64 + warp * 16 + g;
                Ps[r][nt * 4 + tg]     = pack_half2(e00, e01);
                Ps[r + 8][nt * 4 + tg] = pack_half2(e10, e11);
            }
            lsum[h][0] = lsum[h][0] * alpha[h][0] + ps0;
            lsum[h][1] = lsum[h][1] * alpha[h][1] + ps1;
            mprev[h][0] = mn0; mprev[h][1] = mn1;
        }
        __syncwarp();   // P writes visible before ldmatrix reads (warp-local rows)

        // O *= alpha — skipped when alpha == 1 exactly for the whole warp
        // (expf(0) == 1.0f exact; identical numerics on the skip path)
        bool need = (alpha[0][0] != 1.f) | (alpha[0][1] != 1.f) |
                    (alpha[1][0] != 1.f) | (alpha[1][1] != 1.f);
        if (__any_sync(0xffffffffu, need)) {
            #pragma unroll
            for (int h = 0; h < 2; h++)
                #pragma unroll
                for (int nt = 0; nt < 8; nt++) {
                    o[h][nt][0] *= alpha[h][0]; o[h][nt][1] *= alpha[h][0];
                    o[h][nt][2] *= alpha[h][1]; o[h][nt][3] *= alpha[h][1];
                }
        }
        // O += P V  (2 k16 steps over 32 keys)
        #pragma unroll
        for (int ks = 0; ks < 2; ks++) {
            uint32_t vb[8][2];
            #pragma unroll
            for (int ntp = 0; ntp < 4; ntp++)
                ldsm_x4(vb[2 * ntp][0], vb[2 * ntp][1], vb[2 * ntp + 1][0], vb[2 * ntp + 1][1],
                        vS + ntp * 16 * 80 + ks * 32);
            #pragma unroll
            for (int h = 0; h < 2; h++) {
                uint32_t af[4];
                ldsm_x4(af[0], af[1], af[2], af[3],
                        pAddr0 + (h * 64 + warp * 16) * 80 + ks * 32);
                #pragma unroll
                for (int nt = 0; nt < 8; nt++)
                    mma_f16(o[h][nt], af, vb[nt][0], vb[nt][1]);
            }
        }
        __syncwarp();
    }

    #pragma unroll
    for (int h = 0; h < 2; h++) {
        float l0 = lsum[h][0], l1 = lsum[h][1];
        l0 += __shfl_xor_sync(0xffffffffu, l0, 1);
        l0 += __shfl_xor_sync(0xffffffffu, l0, 2);
        l1 += __shfl_xor_sync(0xffffffffu, l1, 1);
        l1 += __shfl_xor_sync(0xffffffffu, l1, 2);
        float inv0 = 1.0f / l0, inv1 = 1.0f / l1;

        int r0 = q0 + h * 64 + warp * 16 + g;
        #pragma unroll
        for (int nt = 0; nt < 8; nt++) {
            int c = qcol + nt * 8 + 2 * tg;
            *reinterpret_cast<__half2*>(out16 + (base + r0) * DD + c) =
                __floats2half2_rn(o[h][nt][0] * inv0, o[h][nt][1] * inv0);
            *reinterpret_cast<__half2*>(out16 + (base + r0 + 8) * DD + c) =
                __floats2half2_rn(o[h][nt][2] * inv1, o[h][nt][3] * inv1);
        }
    }
}

// ---------------- residual add + LayerNorm (fp32 + optional fp16 out) -----
__device__ __forceinline__ float block_reduce_256(float v, float* red) {
    __syncthreads();
    int t = threadIdx.x;
    #pragma unroll
    for (int o = 16; o > 0; o >>= 1) v += __shfl_down_sync(0xffffffffu, v, o);
    if ((t & 31) == 0) red[t >> 5] = v;
    __syncthreads();
    if (t < 8) {
        v = red[t];
        #pragma unroll
        for (int o = 4; o > 0; o >>= 1) v += __shfl_down_sync(0xffu, v, o);
        if (t == 0) red[0] = v;
    }
    __syncthreads();
    return red[0];
}

template<bool OUT16>
__global__ void add_ln_kernel(const float* __restrict__ A,
                              float* __restrict__ X,
                              __half* __restrict__ X16,
                              const float* __restrict__ g,
                              const float* __restrict__ bt) {
    __shared__ float red[32];
    int r = blockIdx.x, t = threadIdx.x;
    const float* a = A + (size_t)r * DD;
    float* x = X + (size_t)r * DD;
    int d0 = t * 4;
    float4 av = *reinterpret_cast<const float4*>(a + d0);
    float4 xv = *reinterpret_cast<const float4*>(x + d0);
    float v[4] = {av.x + xv.x, av.y + xv.y, av.z + xv.z, av.w + xv.w};
    float sum = v[0] + v[1] + v[2] + v[3];
    sum = block_reduce_256(sum, red);
    float mu = sum * (1.0f / DD);
    float vs = 0.f;
    #pragma unroll
    for (int i = 0; i < 4; i++) { float dl = v[i] - mu; vs += dl * dl; }
    vs = block_reduce_256(vs, red);
    float rs = rsqrtf(vs * (1.0f / DD) + 1e-5f);
    float o[4];
    #pragma unroll
    for (int i = 0; i < 4; i++)
        o[i] = (v[i] - mu) * rs * g[d0 + i] + bt[d0 + i];
    *reinterpret_cast<float4*>(x + d0) = make_float4(o[0], o[1], o[2], o[3]);
    if (OUT16) {
        __half* x16 = X16 + (size_t)r * DD + d0;
        *reinterpret_cast<__half2*>(x16)     = __floats2half2_rn(o[0], o[1]);
        *reinterpret_cast<__half2*>(x16 + 2) = __floats2half2_rn(o[2], o[3]);
    }
}

// ---------------- masked max-pool over sequence ----------------
__global__ void pool_partial_kernel(const float* __restrict__ X,
                                    const int* __restrict__ mask,
                                    float* __restrict__ part) {
    int b = blockIdx.y, ch = blockIdx.x;
    int d = threadIdx.x;
    float m = -INFINITY;
    for (int s = 0; s < 128; s++) {
        int srow = ch * 128 + s;
        float val = X[((size_t)b * SS + srow) * DD + d];
        if (mask[b * SS + srow] != 0) m = fmaxf(m, val);
    }
    part[((size_t)b * 16 + ch) * DD + d] = m;
}

__global__ void pool_final_kernel(const float* __restrict__ part,
                                  float* __restrict__ pooled) {
    int b = blockIdx.x, d = threadIdx.x;
    float m = -INFINITY;
    for (int c = 0; c < 16; c++)
        m = fmaxf(m, part[((size_t)b * 16 + c) * DD + d]);
    pooled[b * DD + d] = m;
}

// ---------------- small head FC ----------------
__global__ void head_fc_kernel(const float* __restrict__ in,
                               const float* __restrict__ W,
                               const float* __restrict__ bias,
                               float* __restrict__ out,
                               int K, int apply_gelu) {
    __shared__ float red[4];
    int n = blockIdx.x, b = blockIdx.y, t = threadIdx.x;
    int N = gridDim.x;
    const float* ip = in + (size_t)b * K;
    const float* wp = W + (size_t)n * K;
    float s = 0.f;
    for (int k = t; k < K; k += 128) s += ip[k] * wp[k];
    #pragma unroll
    for (int o = 16; o > 0; o >>= 1) s += __shfl_down_sync(0xffffffffu, s, o);
    if ((t & 31) == 0) red[t >> 5] = s;
    __syncthreads();
    if (t == 0) {
        float v = red[0] + red[1] + red[2] + red[3] + bias[n];
        if (apply_gelu) v = gelu_exact(v);
        out[b * N + n] = v;
    }
}

// ---------------- launch ----------------
extern "C" void kernel_launch(void* const* d_in, const int* in_sizes, int n_in,
                              void* d_out, int out_size) {
    const int*   x_ids  = (const int*)d_in[0];
    const int*   mask   = (const int*)d_in[1];
    const float* emb    = (const float*)d_in[2];
    const float* qkv_w  = (const float*)d_in[3];
    const float* fc_w   = (const float*)d_in[4];
    const float* fc_b   = (const float*)d_in[5];
    const float* ln1_g  = (const float*)d_in[6];
    const float* ln1_b  = (const float*)d_in[7];
    const float* ffn_w1 = (const float*)d_in[8];
    const float* ffn_b1 = (const float*)d_in[9];
    const float* ffn_w2 = (const float*)d_in[10];
    const float* ffn_b2 = (const float*)d_in[11];
    const float* ln2_g  = (const float*)d_in[12];
    const float* ln2_b  = (const float*)d_in[13];
    const float* pr_w1  = (const float*)d_in[14];
    const float* pr_b1  = (const float*)d_in[15];
    const float* pr_w2  = (const float*)d_in[16];
    const float* pr_b2  = (const float*)d_in[17];
    float* out = (float*)d_out;

    float *X, *O, *part, *pool, *hh;
    __half *X16, *QKV16, *Vt16, *AO16, *H16, *Wq16, *Wf16, *W116, *W216;
    cudaGetSymbolAddress((void**)&X,     g_X);
    cudaGetSymbolAddress((void**)&O,     g_O);
    cudaGetSymbolAddress((void**)&X16,   g_X16);
    cudaGetSymbolAddress((void**)&QKV16, g_QKV16);
    cudaGetSymbolAddress((void**)&Vt16,  g_Vt16);
    cudaGetSymbolAddress((void**)&AO16,  g_AO16);
    cudaGetSymbolAddress((void**)&H16,   g_H16);
    cudaGetSymbolAddress((void**)&Wq16,  g_Wq16);
    cudaGetSymbolAddress((void**)&Wf16,  g_Wf16);
    cudaGetSymbolAddress((void**)&W116,  g_W116);
    cudaGetSymbolAddress((void**)&W216,  g_W216);
    cudaGetSymbolAddress((void**)&part,  g_part);
    cudaGetSymbolAddress((void**)&pool,  g_pool);
    cudaGetSymbolAddress((void**)&hh,    g_hh);

    // 0. convert weights to fp16
    f2h_kernel<<<(3 * DD * DD / 4 + 255) / 256, 256>>>(qkv_w,  Wq16, 3 * DD * DD);
    f2h_kernel<<<(DD * DD / 4 + 255) / 256, 256>>>(fc_w,   Wf16, DD * DD);
    f2h_kernel<<<(FFN * DD / 4 + 255) / 256, 256>>>(ffn_w1, W116, FFN * DD);
    f2h_kernel<<<(DD * FFN / 4 + 255) / 256, 256>>>(ffn_w2, W216, DD * FFN);

    // 1. embedding + positional encoding (fp32 + fp16)
    embed_pe_kernel<<<(NTOK * (DD / 2)) / 256, 256>>>(x_ids, emb, X, X16);

    // 2. QKV projection -> fp16
    gemm_f16_kernel<0, true><<<dim3(3 * DD / 128, NTOK / 128), 128>>>(
        X16, Wq16, nullptr, nullptr, QKV16, NTOK, 3 * DD, DD);

    // 2b. transpose V
    transpose_v_kernel<<<dim3(SS / 32, HDIM / 32, BB * HH), dim3(32, 8)>>>(QKV16, Vt16);

    // 3. attention (fp16 MMA + ldmatrix + alpha-skip)
    flash_f16_kernel<<<dim3(SS / 128, HH, BB), 128>>>(QKV16, Vt16, mask, AO16);

    // 4. output projection (+bias) -> fp32
    gemm_f16_kernel<1, false><<<dim3(DD / 128, NTOK / 128), 128>>>(
        AO16, Wf16, fc_b, O, nullptr, NTOK, DD, DD);

    // 5. residual + LN1 (fp32 X + fp16 copy)
    add_ln_kernel<true><<<NTOK, 256>>>(O, X, X16, ln1_g, ln1_b);

    // 6. FFN up (+bias, gelu) -> fp16
    gemm_f16_kernel<2, true><<<dim3(FFN / 128, NTOK / 128), 128>>>(
        X16, W116, ffn_b1, nullptr, H16, NTOK, FFN, DD);

    // 7. FFN down (+bias) -> fp32
    gemm_f16_kernel<1, false><<<dim3(DD / 128, NTOK / 128), 128>>>(
        H16, W216, ffn_b2, O, nullptr, NTOK, DD, FFN);

    // 8. residual + LN2 (fp32 only)
    add_ln_kernel<false><<<NTOK, 256>>>(O, X, nullptr, ln2_g, ln2_b);

    // 9. masked max-pool
    pool_partial_kernel<<<dim3(16, BB), 1024>>>(X, mask, part);
    pool_final_kernel<<<BB, 1024>>>(part, pool);

    // 10. prediction head
    head_fc_kernel<<<dim3(DD, BB), 128>>>(pool, pr_w1, pr_b1, hh, DD, 1);
    head_fc_kernel<<<dim3(10, BB), 128>>>(hh, pr_w2, pr_b2, out, DD, 0);
}

// round 16
// speedup vs baseline: 1.1178x; 1.0307x over previous
#include <cuda_runtime.h>
#include <cuda_fp16.h>
#include <math.h>
#include <stdint.h>

// Problem constants
#define BB 4
#define SS 2048
#define DD 1024
#define HH 16
#define HDIM 64
#define FFN 2048
#define NTOK (BB*SS)          // 8192

// ---------------- scratch (device globals: allocation-free) ----------------
__device__ float  g_X   [NTOK * DD];          // fp32 residual stream
__device__ float  g_O   [NTOK * DD];          // fp32 gemm output
__device__ __half g_X16 [NTOK * DD];          // fp16 activation copy
__device__ __half g_QKV16[NTOK * 3 * DD];
__device__ __half g_AO16 [NTOK * DD];
__device__ __half g_H16  [NTOK * FFN];
__device__ __half g_Wq16 [3 * DD * DD];
__device__ __half g_Wf16 [DD * DD];
__device__ __half g_W116 [FFN * DD];
__device__ __half g_W216 [DD * FFN];
__device__ float  g_part[BB * 16 * DD];
__device__ float  g_pool[BB * DD];
__device__ float  g_hh  [BB * DD];

__device__ __forceinline__ float gelu_exact(float v) {
    return 0.5f * v * (1.0f + erff(v * 0.7071067811865476f));
}

__device__ __forceinline__ uint32_t smem_u32(const void* p) {
    return (uint32_t)__cvta_generic_to_shared(p);
}
__device__ __forceinline__ void cp16(uint32_t dst, const void* src) {
    asm volatile("cp.async.cg.shared.global [%0], [%1], 16;" :: "r"(dst), "l"(src));
}
__device__ __forceinline__ void cp_commit() {
    asm volatile("cp.async.commit_group;");
}
template<int N>
__device__ __forceinline__ void cp_wait() {
    asm volatile("cp.async.wait_group %0;" :: "n"(N));
}

// fp16 MMA, fp32 accumulate: m16n8k16
__device__ __forceinline__ void mma_f16(float* d, const uint32_t* a, uint32_t b0, uint32_t b1) {
    asm volatile(
        "mma.sync.aligned.m16n8k16.row.col.f32.f16.f16.f32 "
        "{%0,%1,%2,%3}, {%4,%5,%6,%7}, {%8,%9}, {%0,%1,%2,%3};\n"
        : "+f"(d[0]), "+f"(d[1]), "+f"(d[2]), "+f"(d[3])
        : "r"(a[0]), "r"(a[1]), "r"(a[2]), "r"(a[3]), "r"(b0), "r"(b1));
}

// non-trans ldmatrix x4: A-type ([m][k] rows) and B-type stored as [n][k] rows
__device__ __forceinline__ void ldsm_x4(uint32_t& r0, uint32_t& r1, uint32_t& r2, uint32_t& r3,
                                        uint32_t addr) {
    asm volatile("ldmatrix.sync.aligned.m8n8.x4.shared.b16 {%0,%1,%2,%3}, [%4];"
                 : "=r"(r0), "=r"(r1), "=r"(r2), "=r"(r3) : "r"(addr));
}
// trans ldmatrix x4: B-type from [k][n]-rows smem (V in natural [seq][dim] layout)
__device__ __forceinline__ void ldsm_x4_t(uint32_t& r0, uint32_t& r1, uint32_t& r2, uint32_t& r3,
                                          uint32_t addr) {
    asm volatile("ldmatrix.sync.aligned.m8n8.x4.trans.shared.b16 {%0,%1,%2,%3}, [%4];"
                 : "=r"(r0), "=r"(r1), "=r"(r2), "=r"(r3) : "r"(addr));
}

__device__ __forceinline__ uint32_t pack_half2(float a, float b) {
    __half2 h = __floats2half2_rn(a, b);
    uint32_t u;
    memcpy(&u, &h, 4);
    return u;
}

// ---------------- fp32 -> fp16 weight conversion (all 4 weights fused) ----
// Regions (elems/4 chunks): Wq 3M, Wf 1M, W1 2M, W2 2M  -> 2M chunks total
__global__ void f2h_all_kernel(const float* __restrict__ wq, __half* __restrict__ oq,
                               const float* __restrict__ wf, __half* __restrict__ of,
                               const float* __restrict__ w1, __half* __restrict__ o1,
                               const float* __restrict__ w2, __half* __restrict__ o2) {
    int c = blockIdx.x * blockDim.x + threadIdx.x;   // chunk id (4 floats)
    const int nq = 3 * DD * DD / 4, nf = DD * DD / 4, n1 = FFN * DD / 4;
    const float* in; __half* out; int i;
    if (c < nq)                      { in = wq; out = oq; i = c; }
    else if ((c -= nq) < nf)         { in = wf; out = of; i = c; }
    else if ((c -= nf) < n1)         { in = w1; out = o1; i = c; }
    else                             { in = w2; out = o2; i = c - n1; }
    i *= 4;
    float4 v = *reinterpret_cast<const float4*>(in + i);
    *reinterpret_cast<__half2*>(out + i)     = __floats2half2_rn(v.x, v.y);
    *reinterpret_cast<__half2*>(out + i + 2) = __floats2half2_rn(v.z, v.w);
}

// ---------------- embedding + positional encoding (fp32 + fp16) -----------
__global__ void embed_pe_kernel(const int* __restrict__ ids,
                                const float* __restrict__ emb,
                                float* __restrict__ X,
                                __half* __restrict__ X16) {
    int idx = blockIdx.x * blockDim.x + threadIdx.x;
    if (idx >= NTOK * (DD / 2)) return;
    int row = idx >> 9;
    int p   = idx & 511;
    int s   = row & (SS - 1);
    int id  = ids[row];
    float freq = expf(-0.017988946039015358f * (float)p);  // 2*ln(1e4)/1024
    float sv, cv;
    sincosf((float)s * freq, &sv, &cv);
    size_t eo = (size_t)id * DD + 2 * p;
    size_t xo = (size_t)row * DD + 2 * p;
    float v0 = emb[eo] + sv, v1 = emb[eo + 1] + cv;
    X[xo] = v0; X[xo + 1] = v1;
    *reinterpret_cast<__half2*>(X16 + xo) = __floats2half2_rn(v0, v1);
}

// ---------------- fp16 tensor-core GEMM: C = A(MxK) * W(NxK)^T ------------
// BM=BN=128, BK=16, 128 threads (4 warps 2x2), warp tile 64x64, k16 MMA.
// (R13-proven configuration: static smem, 3-stage, wait<1>.)
template<int EPI, bool OUT16>   // EPI: 0 none, 1 +bias, 2 gelu(+bias)
__launch_bounds__(128, 2)
__global__ void gemm_f16_kernel(const __half* __restrict__ A,
                                const __half* __restrict__ W,
                                const float* __restrict__ bias,
                                float* __restrict__ Cf,
                                __half* __restrict__ Ch,
                                int M, int N, int K) {
    __shared__ __align__(16) uint32_t As[3][128][12];   // 8 u32 used, row stride 48B
    __shared__ __align__(16) uint32_t Ws[3][128][12];

    const int tid  = threadIdx.x;
    const int lane = tid & 31, warp = tid >> 5;
    const int wm = warp >> 1, wn = warp & 1;
    const int wrow = wm * 64, wcol = wn * 64;
    const int m0 = blockIdx.y * 128, n0 = blockIdx.x * 128;
    const int g = lane >> 2, tg = lane & 3;

    const int lrow = lane & 7, sel = lane >> 3;
    const uint32_t aAddr0 = smem_u32(&As[0][wrow + lrow + (sel & 1) * 8][(sel >> 1) * 4]);
    const uint32_t bAddr0 = smem_u32(&Ws[0][wcol + lrow + ((sel >> 1) & 1) * 8][(sel & 1) * 4]);
    const uint32_t stageB = 128 * 48;    // 6144 bytes per stage

    auto issue = [&](int st, int k0) {
        int r = tid;   // 0..127, one row each
        const __half* a = A + (size_t)(m0 + r) * K + k0;
        cp16(smem_u32(&As[st][r][0]), a);
        cp16(smem_u32(&As[st][r][4]), a + 8);
        const __half* w = W + (size_t)(n0 + r) * K + k0;
        cp16(smem_u32(&Ws[st][r][0]), w);
        cp16(smem_u32(&Ws[st][r][4]), w + 8);
    };

    float acc[4][8][4];
    #pragma unroll
    for (int mt = 0; mt < 4; mt++)
        #pragma unroll
        for (int nt = 0; nt < 8; nt++)
            #pragma unroll
            for (int r = 0; r < 4; r++) acc[mt][nt][r] = 0.f;

    const int nIter = K / 16;
    issue(0, 0);  cp_commit();
    issue(1, 16); cp_commit();

    for (int it = 0; it < nIter; it++) {
        if (it == nIter - 1) cp_wait<0>(); else cp_wait<1>();
        __syncthreads();
        if (it + 2 < nIter) { issue((it + 2) % 3, (it + 2) * 16); cp_commit(); }
        const int st = it % 3;
        const uint32_t aS = aAddr0 + st * stageB;
        const uint32_t bS = bAddr0 + st * stageB;

        uint32_t af[4][4], bf[8][2];
        #pragma unroll
        for (int mt = 0; mt < 4; mt++)
            ldsm_x4(af[mt][0], af[mt][1], af[mt][2], af[mt][3], aS + mt * 16 * 48);
        #pragma unroll
        for (int ntp = 0; ntp < 4; ntp++)
            ldsm_x4(bf[2 * ntp][0], bf[2 * ntp][1], bf[2 * ntp + 1][0], bf[2 * ntp + 1][1],
                    bS + ntp * 16 * 48);
        #pragma unroll
        for (int mt = 0; mt < 4; mt++)
            #pragma unroll
            for (int nt = 0; nt < 8; nt++)
                mma_f16(acc[mt][nt], af[mt], bf[nt][0], bf[nt][1]);
    }

    // epilogue
    #pragma unroll
    for (int mt = 0; mt < 4; mt++) {
        int r0 = m0 + wrow + mt * 16 + g;
        #pragma unroll
        for (int nt = 0; nt < 8; nt++) {
            int c = n0 + wcol + nt * 8 + 2 * tg;
            float b0 = 0.f, b1 = 0.f;
            if (EPI >= 1) { b0 = bias[c]; b1 = bias[c + 1]; }
            float v00 = acc[mt][nt][0] + b0, v01 = acc[mt][nt][1] + b1;
            float v10 = acc[mt][nt][2] + b0, v11 = acc[mt][nt][3] + b1;
            if (EPI == 2) {
                v00 = gelu_exact(v00); v01 = gelu_exact(v01);
                v10 = gelu_exact(v10); v11 = gelu_exact(v11);
            }
            if (OUT16) {
                *reinterpret_cast<__half2*>(Ch + (size_t)r0 * N + c)       = __floats2half2_rn(v00, v01);
                *reinterpret_cast<__half2*>(Ch + (size_t)(r0 + 8) * N + c) = __floats2half2_rn(v10, v11);
            } else {
                *reinterpret_cast<float2*>(Cf + (size_t)r0 * N + c)       = make_float2(v00, v01);
                *reinterpret_cast<float2*>(Cf + (size_t)(r0 + 8) * N + c) = make_float2(v10, v11);
            }
        }
    }
}

// ---------------- fp16 flash attention, 128-query tiles, ldmatrix ---------
// V loaded directly from qkv16 ([seq][dim] rows, like K); PV B-fragments via
// ldmatrix.x4.trans. No separate V transpose pass.
__launch_bounds__(128, 2)
__global__ void flash_f16_kernel(const __half* __restrict__ qkv16,
                                 const int* __restrict__ mask,
                                 __half* __restrict__ out16) {
    __shared__ __align__(16) uint32_t Ks[3][32][36];   // keys x dim-u32 (144B rows); also Q staging
    __shared__ __align__(16) uint32_t Vs[3][32][36];   // keys x dim-u32 (144B rows), natural layout
    __shared__ __align__(16) uint32_t Ps[128][20];     // q-rows x key-u32 fp16 (80B rows)
    __shared__ __align__(16) int msk[3][32];

    const int b = blockIdx.z, h_ = blockIdx.y;
    const int q0 = blockIdx.x * 128;
    const int tid = threadIdx.x, lane = tid & 31, warp = tid >> 5;
    const int g = lane >> 2, tg = lane & 3;
    const size_t base = (size_t)b * SS;
    const int qcol = h_ * HDIM;

    const int lrow = lane & 7, sel = lane >> 3;
    // K non-trans B-type base ([n=key][k=dim] rows)
    const uint32_t kAddr0 = smem_u32(&Ks[0][lrow + ((sel >> 1) & 1) * 8][(sel & 1) * 4]);
    // V trans B-type base ([k=key][n=dim] rows): lane groups address tiles
    // (k0-7/n0-7), (k8-15/n0-7), (k0-7/n8-15), (k8-15/n8-15)
    const uint32_t vAddr0 = smem_u32(&Vs[0][lrow + (sel & 1) * 8][(sel >> 1) * 4]);
    // P x4 base (A-type)
    const uint32_t pAddr0 = smem_u32(&Ps[lrow + (sel & 1) * 8][(sel >> 1) * 4]);
    const uint32_t kvStage = 32 * 144;

    // stage Q fp16 in two 64-row halves through the Ks region
    uint32_t* qst = &Ks[0][0][0];        // viewed as [64][36]
    uint32_t qf[2][4][4];
    #pragma unroll
    for (int half = 0; half < 2; half++) {
        #pragma unroll
        for (int i = 0; i < 4; i++) {
            int idx = tid + 128 * i;      // 512 16B-chunks = 64 rows x 8
            int r = idx >> 3, cj = idx & 7;
            uint4 v = *reinterpret_cast<const uint4*>(
                qkv16 + (base + q0 + half * 64 + r) * (3 * DD) + qcol + cj * 8);
            *reinterpret_cast<uint4*>(&qst[r * 36 + cj * 4]) = v;
        }
        __syncthreads();
        #pragma unroll
        for (int ks = 0; ks < 4; ks++) {
            int r = warp * 16 + g;
            qf[half][ks][0] = qst[r * 36 + ks * 8 + tg];
            qf[half][ks][1] = qst[(r + 8) * 36 + ks * 8 + tg];
            qf[half][ks][2] = qst[r * 36 + ks * 8 + tg + 4];
            qf[half][ks][3] = qst[(r + 8) * 36 + ks * 8 + tg + 4];
        }
        __syncthreads();
    }

    auto issueKV = [&](int st, int kc) {
        #pragma unroll
        for (int i = 0; i < 2; i++) {
            int e = tid + 128 * i;         // 0..255
            int r = e >> 3, cj = e & 7;
            const __half* src = qkv16 + (base + kc + r) * (3 * DD) + qcol + cj * 8;
            cp16(smem_u32(&Ks[st][r][cj * 4]), src + DD);
            cp16(smem_u32(&Vs[st][r][cj * 4]), src + 2 * DD);
        }
        if (tid < 8) cp16(smem_u32(&msk[st][tid * 4]), mask + b * SS + kc + tid * 4);
    };

    float o[2][8][4];
    #pragma unroll
    for (int h = 0; h < 2; h++)
        #pragma unroll
        for (int nt = 0; nt < 8; nt++)
            #pragma unroll
            for (int r = 0; r < 4; r++) o[h][nt][r] = 0.f;
    float mprev[2][2] = {{-1e30f, -1e30f}, {-1e30f, -1e30f}};
    float lsum[2][2]  = {{0.f, 0.f}, {0.f, 0.f}};

    const int nIter = SS / 32;   // 64
    issueKV(0, 0);  cp_commit();
    issueKV(1, 32); cp_commit();

    for (int it = 0; it < nIter; it++) {
        if (it == nIter - 1) cp_wait<0>(); else cp_wait<1>();
        __syncthreads();
        if (it + 2 < nIter) { issueKV((it + 2) % 3, (it + 2) * 32); cp_commit(); }
        const int st = it % 3;
        const uint32_t kS = kAddr0 + st * kvStage;
        const uint32_t vS = vAddr0 + st * kvStage;

        // S = Q K^T (4 k16 steps over 64 dims)
        float s[2][4][4];
        #pragma unroll
        for (int h = 0; h < 2; h++)
            #pragma unroll
            for (int nt = 0; nt < 4; nt++)
                #pragma unroll
                for (int r = 0; r < 4; r++) s[h][nt][r] = 0.f;
        #pragma unroll
        for (int ks = 0; ks < 4; ks++) {
            uint32_t kb[4][2];
            ldsm_x4(kb[0][0], kb[0][1], kb[1][0], kb[1][1], kS + ks * 32);
            ldsm_x4(kb[2][0], kb[2][1], kb[3][0], kb[3][1], kS + 16 * 144 + ks * 32);
            #pragma unroll
            for (int h = 0; h < 2; h++)
                #pragma unroll
                for (int nt = 0; nt < 4; nt++)
                    mma_f16(s[h][nt], qf[h][ks], kb[nt][0], kb[nt][1]);
        }

        // scale + mask + online softmax per half
        float alpha[2][2];
        #pragma unroll
        for (int h = 0; h < 2; h++) {
            float mx0 = -1e30f, mx1 = -1e30f;
            #pragma unroll
            for (int nt = 0; nt < 4; nt++) {
                int c = nt * 8 + 2 * tg;
                s[h][nt][0] *= 0.125f; s[h][nt][1] *= 0.125f;
                s[h][nt][2] *= 0.125f; s[h][nt][3] *= 0.125f;
                if (msk[st][c] == 0)     { s[h][nt][0] = -1e30f; s[h][nt][2] = -1e30f; }
                if (msk[st][c + 1] == 0) { s[h][nt][1] = -1e30f; s[h][nt][3] = -1e30f; }
                mx0 = fmaxf(mx0, fmaxf(s[h][nt][0], s[h][nt][1]));
                mx1 = fmaxf(mx1, fmaxf(s[h][nt][2], s[h][nt][3]));
            }
            mx0 = fmaxf(mx0, __shfl_xor_sync(0xffffffffu, mx0, 1));
            mx0 = fmaxf(mx0, __shfl_xor_sync(0xffffffffu, mx0, 2));
            mx1 = fmaxf(mx1, __shfl_xor_sync(0xffffffffu, mx1, 1));
            mx1 = fmaxf(mx1, __shfl_xor_sync(0xffffffffu, mx1, 2));

            float mn0 = fmaxf(mprev[h][0], mx0), mn1 = fmaxf(mprev[h][1], mx1);
            alpha[h][0] = __expf(mprev[h][0] - mn0);
            alpha[h][1] = __expf(mprev[h][1] - mn1);

            float ps0 = 0.f, ps1 = 0.f;
            #pragma unroll
            for (int nt = 0; nt < 4; nt++) {
                float e00 = __expf(s[h][nt][0] - mn0);
                float e01 = __expf(s[h][nt][1] - mn0);
                float e10 = __expf(s[h][nt][2] - mn1);
                float e11 = __expf(s[h][nt][3] - mn1);
                ps0 += e00 + e01;
                ps1 += e10 + e11;
                int r = h * 64 + warp * 16 + g;
                Ps[r][nt * 4 + tg]     = pack_half2(e00, e01);
                Ps[r + 8][nt * 4 + tg] = pack_half2(e10, e11);
            }
            lsum[h][0] = lsum[h][0] * alpha[h][0] + ps0;
            lsum[h][1] = lsum[h][1] * alpha[h][1] + ps1;
            mprev[h][0] = mn0; mprev[h][1] = mn1;
        }
        __syncwarp();   // P writes visible before ldmatrix reads (warp-local rows)

        // O = O*alpha + P V  (2 k16 steps over 32 keys)
        #pragma unroll
        for (int h = 0; h < 2; h++)
            #pragma unroll
            for (int nt = 0; nt < 8; nt++) {
                o[h][nt][0] *= alpha[h][0]; o[h][nt][1] *= alpha[h][0];
                o[h][nt][2] *= alpha[h][1]; o[h][nt][3] *= alpha[h][1];
            }
        #pragma unroll
        for (int ks = 0; ks < 2; ks++) {
            uint32_t vb[8][2];
            #pragma unroll
            for (int ntp = 0; ntp < 4; ntp++)
                ldsm_x4_t(vb[2 * ntp][0], vb[2 * ntp][1], vb[2 * ntp + 1][0], vb[2 * ntp + 1][1],
                          vS + ks * 16 * 144 + ntp * 32);
            #pragma unroll
            for (int h = 0; h < 2; h++) {
                uint32_t af[4];
                ldsm_x4(af[0], af[1], af[2], af[3],
                        pAddr0 + (h * 64 + warp * 16) * 80 + ks * 32);
                #pragma unroll
                for (int nt = 0; nt < 8; nt++)
                    mma_f16(o[h][nt], af, vb[nt][0], vb[nt][1]);
            }
        }
        __syncwarp();
    }

    #pragma unroll
    for (int h = 0; h < 2; h++) {
        float l0 = lsum[h][0], l1 = lsum[h][1];
        l0 += __shfl_xor_sync(0xffffffffu, l0, 1);
        l0 += __shfl_xor_sync(0xffffffffu, l0, 2);
        l1 += __shfl_xor_sync(0xffffffffu, l1, 1);
        l1 += __shfl_xor_sync(0xffffffffu, l1, 2);
        float inv0 = 1.0f / l0, inv1 = 1.0f / l1;

        int r0 = q0 + h * 64 + warp * 16 + g;
        #pragma unroll
        for (int nt = 0; nt < 8; nt++) {
            int c = qcol + nt * 8 + 2 * tg;
            *reinterpret_cast<__half2*>(out16 + (base + r0) * DD + c) =
                __floats2half2_rn(o[h][nt][0] * inv0, o[h][nt][1] * inv0);
            *reinterpret_cast<__half2*>(out16 + (base + r0 + 8) * DD + c) =
                __floats2half2_rn(o[h][nt][2] * inv1, o[h][nt][3] * inv1);
        }
    }
}

// ---------------- residual add + LayerNorm (fp32 + optional fp16 out) -----
__device__ __forceinline__ float block_reduce_256(float v, float* red) {
    __syncthreads();
    int t = threadIdx.x;
    #pragma unroll
    for (int o = 16; o > 0; o >>= 1) v += __shfl_down_sync(0xffffffffu, v, o);
    if ((t & 31) == 0) red[t >> 5] = v;
    __syncthreads();
    if (t < 8) {
        v = red[t];
        #pragma unroll
        for (int o = 4; o > 0; o >>= 1) v += __shfl_down_sync(0xffu, v, o);
        if (t == 0) red[0] = v;
    }
    __syncthreads();
    return red[0];
}

template<bool OUT16>
__global__ void add_ln_kernel(const float* __restrict__ A,
                              float* __restrict__ X,
                              __half* __restrict__ X16,
                              const float* __restrict__ g,
                              const float* __restrict__ bt) {
    __shared__ float red[32];
    int r = blockIdx.x, t = threadIdx.x;
    const float* a = A + (size_t)r * DD;
    float* x = X + (size_t)r * DD;
    int d0 = t * 4;
    float4 av = *reinterpret_cast<const float4*>(a + d0);
    float4 xv = *reinterpret_cast<const float4*>(x + d0);
    float v[4] = {av.x + xv.x, av.y + xv.y, av.z + xv.z, av.w + xv.w};
    float sum = v[0] + v[1] + v[2] + v[3];
    sum = block_reduce_256(sum, red);
    float mu = sum * (1.0f / DD);
    float vs = 0.f;
    #pragma unroll
    for (int i = 0; i < 4; i++) { float dl = v[i] - mu; vs += dl * dl; }
    vs = block_reduce_256(vs, red);
    float rs = rsqrtf(vs * (1.0f / DD) + 1e-5f);
    float o[4];
    #pragma unroll
    for (int i = 0; i < 4; i++)
        o[i] = (v[i] - mu) * rs * g[d0 + i] + bt[d0 + i];
    *reinterpret_cast<float4*>(x + d0) = make_float4(o[0], o[1], o[2], o[3]);
    if (OUT16) {
        __half* x16 = X16 + (size_t)r * DD + d0;
        *reinterpret_cast<__half2*>(x16)     = __floats2half2_rn(o[0], o[1]);
        *reinterpret_cast<__half2*>(x16 + 2) = __floats2half2_rn(o[2], o[3]);
    }
}

// ---------------- masked max-pool over sequence ----------------
__global__ void pool_partial_kernel(const float* __restrict__ X,
                                    const int* __restrict__ mask,
                                    float* __restrict__ part) {
    int b = blockIdx.y, ch = blockIdx.x;
    int d = threadIdx.x;
    float m = -INFINITY;
    for (int s = 0; s < 128; s++) {
        int srow = ch * 128 + s;
        float val = X[((size_t)b * SS + srow) * DD + d];
        if (mask[b * SS + srow] != 0) m = fmaxf(m, val);
    }
    part[((size_t)b * 16 + ch) * DD + d] = m;
}

__global__ void pool_final_kernel(const float* __restrict__ part,
                                  float* __restrict__ pooled) {
    int b = blockIdx.x, d = threadIdx.x;
    float m = -INFINITY;
    for (int c = 0; c < 16; c++)
        m = fmaxf(m, part[((size_t)b * 16 + c) * DD + d]);
    pooled[b * DD + d] = m;
}

// ---------------- small head FC ----------------
__global__ void head_fc_kernel(const float* __restrict__ in,
                               const float* __restrict__ W,
                               const float* __restrict__ bias,
                               float* __restrict__ out,
                               int K, int apply_gelu) {
    __shared__ float red[4];
    int n = blockIdx.x, b = blockIdx.y, t = threadIdx.x;
    int N = gridDim.x;
    const float* ip = in + (size_t)b * K;
    const float* wp = W + (size_t)n * K;
    float s = 0.f;
    for (int k = t; k < K; k += 128) s += ip[k] * wp[k];
    #pragma unroll
    for (int o = 16; o > 0; o >>= 1) s += __shfl_down_sync(0xffffffffu, s, o);
    if ((t & 31) == 0) red[t >> 5] = s;
    __syncthreads();
    if (t == 0) {
        float v = red[0] + red[1] + red[2] + red[3] + bias[n];
        if (apply_gelu) v = gelu_exact(v);
        out[b * N + n] = v;
    }
}

// ---------------- launch ----------------
extern "C" void kernel_launch(void* const* d_in, const int* in_sizes, int n_in,
                              void* d_out, int out_size) {
    const int*   x_ids  = (const int*)d_in[0];
    const int*   mask   = (const int*)d_in[1];
    const float* emb    = (const float*)d_in[2];
    const float* qkv_w  = (const float*)d_in[3];
    const float* fc_w   = (const float*)d_in[4];
    const float* fc_b   = (const float*)d_in[5];
    const float* ln1_g  = (const float*)d_in[6];
    const float* ln1_b  = (const float*)d_in[7];
    const float* ffn_w1 = (const float*)d_in[8];
    const float* ffn_b1 = (const float*)d_in[9];
    const float* ffn_w2 = (const float*)d_in[10];
    const float* ffn_b2 = (const float*)d_in[11];
    const float* ln2_g  = (const float*)d_in[12];
    const float* ln2_b  = (const float*)d_in[13];
    const float* pr_w1  = (const float*)d_in[14];
    const float* pr_b1  = (const float*)d_in[15];
    const float* pr_w2  = (const float*)d_in[16];
    const float* pr_b2  = (const float*)d_in[17];
    float* out = (float*)d_out;

    float *X, *O, *part, *pool, *hh;
    __half *X16, *QKV16, *AO16, *H16, *Wq16, *Wf16, *W116, *W216;
    cudaGetSymbolAddress((void**)&X,     g_X);
    cudaGetSymbolAddress((void**)&O,     g_O);
    cudaGetSymbolAddress((void**)&X16,   g_X16);
    cudaGetSymbolAddress((void**)&QKV16, g_QKV16);
    cudaGetSymbolAddress((void**)&AO16,  g_AO16);
    cudaGetSymbolAddress((void**)&H16,   g_H16);
    cudaGetSymbolAddress((void**)&Wq16,  g_Wq16);
    cudaGetSymbolAddress((void**)&Wf16,  g_Wf16);
    cudaGetSymbolAddress((void**)&W116,  g_W116);
    cudaGetSymbolAddress((void**)&W216,  g_W216);
    cudaGetSymbolAddress((void**)&part,  g_part);
    cudaGetSymbolAddress((void**)&pool,  g_pool);
    cudaGetSymbolAddress((void**)&hh,    g_hh);

    // 0. convert all weights to fp16 (single kernel)
    {
        int chunks = (3 * DD * DD + DD * DD + FFN * DD + DD * FFN) / 4;
        f2h_all_kernel<<<(chunks + 255) / 256, 256>>>(
            qkv_w, Wq16, fc_w, Wf16, ffn_w1, W116, ffn_w2, W216);
    }

    // 1. embedding + positional encoding (fp32 + fp16)
    embed_pe_kernel<<<(NTOK * (DD / 2)) / 256, 256>>>(x_ids, emb, X, X16);

    // 2. QKV projection -> fp16
    gemm_f16_kernel<0, true><<<dim3(3 * DD / 128, NTOK / 128), 128>>>(
        X16, Wq16, nullptr, nullptr, QKV16, NTOK, 3 * DD, DD);

    // 3. attention (fp16 MMA; V via ldmatrix.trans directly from QKV)
    flash_f16_kernel<<<dim3(SS / 128, HH, BB), 128>>>(QKV16, mask, AO16);

    // 4. output projection (+bias) -> fp32
    gemm_f16_kernel<1, false><<<dim3(DD / 128, NTOK / 128), 128>>>(
        AO16, Wf16, fc_b, O, nullptr, NTOK, DD, DD);

    // 5. residual + LN1 (fp32 X + fp16 copy)
    add_ln_kernel<true><<<NTOK, 256>>>(O, X, X16, ln1_g, ln1_b);

    // 6. FFN up (+bias, gelu) -> fp16
    gemm_f16_kernel<2, true><<<dim3(FFN / 128, NTOK / 128), 128>>>(
        X16, W116, ffn_b1, nullptr, H16, NTOK, FFN, DD);

    // 7. FFN down (+bias) -> fp32
    gemm_f16_kernel<1, false><<<dim3(DD / 128, NTOK / 128), 128>>>(
        H16, W216, ffn_b2, O, nullptr, NTOK, DD, FFN);

    // 8. residual + LN2 (fp32 only)
    add_ln_kernel<false><<<NTOK, 256>>>(O, X, nullptr, ln2_g, ln2_b);

    // 9. masked max-pool
    pool_partial_kernel<<<dim3(16, BB), 1024>>>(X, mask, part);
    pool_final_kernel<<<BB, 1024>>>(part, pool);

    // 10. prediction head
    head_fc_kernel<<<dim3(DD, BB), 128>>>(pool, pr_w1, pr_b1, hh, DD, 1);
    head_fc_kernel<<<dim3(10, BB), 128>>>(hh, pr_w2, pr_b2, out, DD, 0);
}

// round 17
// speedup vs baseline: 1.1293x; 1.0103x over previous
#include <cuda_runtime.h>
#include <cuda_fp16.h>
#include <math.h>
#include <stdint.h>

// Problem constants
#define BB 4
#define SS 2048
#define DD 1024
#define HH 16
#define HDIM 64
#define FFN 2048
#define NTOK (BB*SS)          // 8192

// ---------------- scratch (device globals: allocation-free) ----------------
__device__ float  g_X   [NTOK * DD];          // fp32 residual stream
__device__ float  g_O   [NTOK * DD];          // fp32 gemm output
__device__ __half g_X16 [NTOK * DD];          // fp16 activation copy
__device__ __half g_QKV16[NTOK * 3 * DD];
__device__ __half g_AO16 [NTOK * DD];
__device__ __half g_H16  [NTOK * FFN];
__device__ __half g_Wq16 [3 * DD * DD];
__device__ __half g_Wf16 [DD * DD];
__device__ __half g_W116 [FFN * DD];
__device__ __half g_W216 [DD * FFN];
__device__ float  g_part[BB * 16 * DD];
__device__ float  g_pool[BB * DD];
__device__ float  g_hh  [BB * DD];

__device__ __forceinline__ float gelu_exact(float v) {
    return 0.5f * v * (1.0f + erff(v * 0.7071067811865476f));
}

__device__ __forceinline__ uint32_t smem_u32(const void* p) {
    return (uint32_t)__cvta_generic_to_shared(p);
}
__device__ __forceinline__ void cp16(uint32_t dst, const void* src) {
    asm volatile("cp.async.cg.shared.global [%0], [%1], 16;" :: "r"(dst), "l"(src));
}
__device__ __forceinline__ void cp_commit() {
    asm volatile("cp.async.commit_group;");
}
template<int N>
__device__ __forceinline__ void cp_wait() {
    asm volatile("cp.async.wait_group %0;" :: "n"(N));
}

// fp16 MMA, fp32 accumulate: m16n8k16
__device__ __forceinline__ void mma_f16(float* d, const uint32_t* a, uint32_t b0, uint32_t b1) {
    asm volatile(
        "mma.sync.aligned.m16n8k16.row.col.f32.f16.f16.f32 "
        "{%0,%1,%2,%3}, {%4,%5,%6,%7}, {%8,%9}, {%0,%1,%2,%3};\n"
        : "+f"(d[0]), "+f"(d[1]), "+f"(d[2]), "+f"(d[3])
        : "r"(a[0]), "r"(a[1]), "r"(a[2]), "r"(a[3]), "r"(b0), "r"(b1));
}

// non-trans ldmatrix x4: A-type ([m][k] rows) and B-type stored as [n][k] rows
__device__ __forceinline__ void ldsm_x4(uint32_t& r0, uint32_t& r1, uint32_t& r2, uint32_t& r3,
                                        uint32_t addr) {
    asm volatile("ldmatrix.sync.aligned.m8n8.x4.shared.b16 {%0,%1,%2,%3}, [%4];"
                 : "=r"(r0), "=r"(r1), "=r"(r2), "=r"(r3) : "r"(addr));
}
// trans ldmatrix x4: B-type from [k][n]-rows smem (V in natural [seq][dim] layout)
__device__ __forceinline__ void ldsm_x4_t(uint32_t& r0, uint32_t& r1, uint32_t& r2, uint32_t& r3,
                                          uint32_t addr) {
    asm volatile("ldmatrix.sync.aligned.m8n8.x4.trans.shared.b16 {%0,%1,%2,%3}, [%4];"
                 : "=r"(r0), "=r"(r1), "=r"(r2), "=r"(r3) : "r"(addr));
}

__device__ __forceinline__ uint32_t pack_half2(float a, float b) {
    __half2 h = __floats2half2_rn(a, b);
    uint32_t u;
    memcpy(&u, &h, 4);
    return u;
}

// ---------------- fp32 -> fp16 weight conversion (all 4 weights fused) ----
__global__ void f2h_all_kernel(const float* __restrict__ wq, __half* __restrict__ oq,
                               const float* __restrict__ wf, __half* __restrict__ of,
                               const float* __restrict__ w1, __half* __restrict__ o1,
                               const float* __restrict__ w2, __half* __restrict__ o2) {
    int c = blockIdx.x * blockDim.x + threadIdx.x;   // chunk id (4 floats)
    const int nq = 3 * DD * DD / 4, nf = DD * DD / 4, n1 = FFN * DD / 4;
    const float* in; __half* out; int i;
    if (c < nq)                      { in = wq; out = oq; i = c; }
    else if ((c -= nq) < nf)         { in = wf; out = of; i = c; }
    else if ((c -= nf) < n1)         { in = w1; out = o1; i = c; }
    else                             { in = w2; out = o2; i = c - n1; }
    i *= 4;
    float4 v = *reinterpret_cast<const float4*>(in + i);
    *reinterpret_cast<__half2*>(out + i)     = __floats2half2_rn(v.x, v.y);
    *reinterpret_cast<__half2*>(out + i + 2) = __floats2half2_rn(v.z, v.w);
}

// ---------------- embedding + positional encoding (fp32 + fp16) -----------
__global__ void embed_pe_kernel(const int* __restrict__ ids,
                                const float* __restrict__ emb,
                                float* __restrict__ X,
                                __half* __restrict__ X16) {
    int idx = blockIdx.x * blockDim.x + threadIdx.x;
    if (idx >= NTOK * (DD / 2)) return;
    int row = idx >> 9;
    int p   = idx & 511;
    int s   = row & (SS - 1);
    int id  = ids[row];
    float freq = expf(-0.017988946039015358f * (float)p);  // 2*ln(1e4)/1024
    float sv, cv;
    sincosf((float)s * freq, &sv, &cv);
    size_t eo = (size_t)id * DD + 2 * p;
    size_t xo = (size_t)row * DD + 2 * p;
    float v0 = emb[eo] + sv, v1 = emb[eo + 1] + cv;
    X[xo] = v0; X[xo + 1] = v1;
    *reinterpret_cast<__half2*>(X16 + xo) = __floats2half2_rn(v0, v1);
}

// ---------------- fp16 tensor-core GEMM: C = A(MxK) * W(NxK)^T ------------
// BM=BN=128, BK=16, 128 threads (4 warps 2x2), warp tile 64x64, k16 MMA.
// (R13-proven configuration: static smem, 3-stage, wait<1>.)
template<int EPI, bool OUT16>   // EPI: 0 none, 1 +bias, 2 gelu(+bias)
__launch_bounds__(128, 2)
__global__ void gemm_f16_kernel(const __half* __restrict__ A,
                                const __half* __restrict__ W,
                                const float* __restrict__ bias,
                                float* __restrict__ Cf,
                                __half* __restrict__ Ch,
                                int M, int N, int K) {
    __shared__ __align__(16) uint32_t As[3][128][12];   // 8 u32 used, row stride 48B
    __shared__ __align__(16) uint32_t Ws[3][128][12];

    const int tid  = threadIdx.x;
    const int lane = tid & 31, warp = tid >> 5;
    const int wm = warp >> 1, wn = warp & 1;
    const int wrow = wm * 64, wcol = wn * 64;
    const int m0 = blockIdx.y * 128, n0 = blockIdx.x * 128;
    const int g = lane >> 2, tg = lane & 3;

    const int lrow = lane & 7, sel = lane >> 3;
    const uint32_t aAddr0 = smem_u32(&As[0][wrow + lrow + (sel & 1) * 8][(sel >> 1) * 4]);
    const uint32_t bAddr0 = smem_u32(&Ws[0][wcol + lrow + ((sel >> 1) & 1) * 8][(sel & 1) * 4]);
    const uint32_t stageB = 128 * 48;    // 6144 bytes per stage

    auto issue = [&](int st, int k0) {
        int r = tid;   // 0..127, one row each
        const __half* a = A + (size_t)(m0 + r) * K + k0;
        cp16(smem_u32(&As[st][r][0]), a);
        cp16(smem_u32(&As[st][r][4]), a + 8);
        const __half* w = W + (size_t)(n0 + r) * K + k0;
        cp16(smem_u32(&Ws[st][r][0]), w);
        cp16(smem_u32(&Ws[st][r][4]), w + 8);
    };

    float acc[4][8][4];
    #pragma unroll
    for (int mt = 0; mt < 4; mt++)
        #pragma unroll
        for (int nt = 0; nt < 8; nt++)
            #pragma unroll
            for (int r = 0; r < 4; r++) acc[mt][nt][r] = 0.f;

    const int nIter = K / 16;
    issue(0, 0);  cp_commit();
    issue(1, 16); cp_commit();

    for (int it = 0; it < nIter; it++) {
        if (it == nIter - 1) cp_wait<0>(); else cp_wait<1>();
        __syncthreads();
        if (it + 2 < nIter) { issue((it + 2) % 3, (it + 2) * 16); cp_commit(); }
        const int st = it % 3;
        const uint32_t aS = aAddr0 + st * stageB;
        const uint32_t bS = bAddr0 + st * stageB;

        uint32_t af[4][4], bf[8][2];
        #pragma unroll
        for (int mt = 0; mt < 4; mt++)
            ldsm_x4(af[mt][0], af[mt][1], af[mt][2], af[mt][3], aS + mt * 16 * 48);
        #pragma unroll
        for (int ntp = 0; ntp < 4; ntp++)
            ldsm_x4(bf[2 * ntp][0], bf[2 * ntp][1], bf[2 * ntp + 1][0], bf[2 * ntp + 1][1],
                    bS + ntp * 16 * 48);
        #pragma unroll
        for (int mt = 0; mt < 4; mt++)
            #pragma unroll
            for (int nt = 0; nt < 8; nt++)
                mma_f16(acc[mt][nt], af[mt], bf[nt][0], bf[nt][1]);
    }

    // epilogue
    #pragma unroll
    for (int mt = 0; mt < 4; mt++) {
        int r0 = m0 + wrow + mt * 16 + g;
        #pragma unroll
        for (int nt = 0; nt < 8; nt++) {
            int c = n0 + wcol + nt * 8 + 2 * tg;
            float b0 = 0.f, b1 = 0.f;
            if (EPI >= 1) { b0 = bias[c]; b1 = bias[c + 1]; }
            float v00 = acc[mt][nt][0] + b0, v01 = acc[mt][nt][1] + b1;
            float v10 = acc[mt][nt][2] + b0, v11 = acc[mt][nt][3] + b1;
            if (EPI == 2) {
                v00 = gelu_exact(v00); v01 = gelu_exact(v01);
                v10 = gelu_exact(v10); v11 = gelu_exact(v11);
            }
            if (OUT16) {
                *reinterpret_cast<__half2*>(Ch + (size_t)r0 * N + c)       = __floats2half2_rn(v00, v01);
                *reinterpret_cast<__half2*>(Ch + (size_t)(r0 + 8) * N + c) = __floats2half2_rn(v10, v11);
            } else {
                *reinterpret_cast<float2*>(Cf + (size_t)r0 * N + c)       = make_float2(v00, v01);
                *reinterpret_cast<float2*>(Cf + (size_t)(r0 + 8) * N + c) = make_float2(v10, v11);
            }
        }
    }
}

// ---------------- fp16 flash attention, 128-query tiles, ldmatrix ---------
// Q pre-scaled by 0.125*log2(e) at staging -> scores in log2 domain; softmax
// uses exp2f (bare EX2, no mul). V via ldmatrix.trans from natural layout.
__launch_bounds__(128, 2)
__global__ void flash_f16_kernel(const __half* __restrict__ qkv16,
                                 const int* __restrict__ mask,
                                 __half* __restrict__ out16) {
    __shared__ __align__(16) uint32_t Ks[3][32][36];   // keys x dim-u32 (144B rows); also Q staging
    __shared__ __align__(16) uint32_t Vs[3][32][36];   // keys x dim-u32 (144B rows), natural layout
    __shared__ __align__(16) uint32_t Ps[128][20];     // q-rows x key-u32 fp16 (80B rows)
    __shared__ __align__(16) int msk[3][32];

    const int b = blockIdx.z, h_ = blockIdx.y;
    const int q0 = blockIdx.x * 128;
    const int tid = threadIdx.x, lane = tid & 31, warp = tid >> 5;
    const int g = lane >> 2, tg = lane & 3;
    const size_t base = (size_t)b * SS;
    const int qcol = h_ * HDIM;

    const int lrow = lane & 7, sel = lane >> 3;
    const uint32_t kAddr0 = smem_u32(&Ks[0][lrow + ((sel >> 1) & 1) * 8][(sel & 1) * 4]);
    const uint32_t vAddr0 = smem_u32(&Vs[0][lrow + (sel & 1) * 8][(sel >> 1) * 4]);
    const uint32_t pAddr0 = smem_u32(&Ps[lrow + (sel & 1) * 8][(sel >> 1) * 4]);
    const uint32_t kvStage = 32 * 144;

    // stage Q fp16 (scaled by 0.125*log2e) in two 64-row halves via Ks region
    const __half2 qscale = __float2half2_rn(0.18033688011112042f);  // 0.125*log2(e)
    uint32_t* qst = &Ks[0][0][0];        // viewed as [64][36]
    uint32_t qf[2][4][4];
    #pragma unroll
    for (int half = 0; half < 2; half++) {
        #pragma unroll
        for (int i = 0; i < 4; i++) {
            int idx = tid + 128 * i;      // 512 16B-chunks = 64 rows x 8
            int r = idx >> 3, cj = idx & 7;
            uint4 v = *reinterpret_cast<const uint4*>(
                qkv16 + (base + q0 + half * 64 + r) * (3 * DD) + qcol + cj * 8);
            __half2* h2 = reinterpret_cast<__half2*>(&v);
            h2[0] = __hmul2(h2[0], qscale);
            h2[1] = __hmul2(h2[1], qscale);
            h2[2] = __hmul2(h2[2], qscale);
            h2[3] = __hmul2(h2[3], qscale);
            *reinterpret_cast<uint4*>(&qst[r * 36 + cj * 4]) = v;
        }
        __syncthreads();
        #pragma unroll
        for (int ks = 0; ks < 4; ks++) {
            int r = warp * 16 + g;
            qf[half][ks][0] = qst[r * 36 + ks * 8 + tg];
            qf[half][ks][1] = qst[(r + 8) * 36 + ks * 8 + tg];
            qf[half][ks][2] = qst[r * 36 + ks * 8 + tg + 4];
            qf[half][ks][3] = qst[(r + 8) * 36 + ks * 8 + tg + 4];
        }
        __syncthreads();
    }

    auto issueKV = [&](int st, int kc) {
        #pragma unroll
        for (int i = 0; i < 2; i++) {
            int e = tid + 128 * i;         // 0..255
            int r = e >> 3, cj = e & 7;
            const __half* src = qkv16 + (base + kc + r) * (3 * DD) + qcol + cj * 8;
            cp16(smem_u32(&Ks[st][r][cj * 4]), src + DD);
            cp16(smem_u32(&Vs[st][r][cj * 4]), src + 2 * DD);
        }
        if (tid < 8) cp16(smem_u32(&msk[st][tid * 4]), mask + b * SS + kc + tid * 4);
    };

    float o[2][8][4];
    #pragma unroll
    for (int h = 0; h < 2; h++)
        #pragma unroll
        for (int nt = 0; nt < 8; nt++)
            #pragma unroll
            for (int r = 0; r < 4; r++) o[h][nt][r] = 0.f;
    float mprev[2][2] = {{-1e30f, -1e30f}, {-1e30f, -1e30f}};
    float lsum[2][2]  = {{0.f, 0.f}, {0.f, 0.f}};

    const int nIter = SS / 32;   // 64
    issueKV(0, 0);  cp_commit();
    issueKV(1, 32); cp_commit();

    for (int it = 0; it < nIter; it++) {
        if (it == nIter - 1) cp_wait<0>(); else cp_wait<1>();
        __syncthreads();
        if (it + 2 < nIter) { issueKV((it + 2) % 3, (it + 2) * 32); cp_commit(); }
        const int st = it % 3;
        const uint32_t kS = kAddr0 + st * kvStage;
        const uint32_t vS = vAddr0 + st * kvStage;

        // S = Q K^T (log2-domain scores; 4 k16 steps over 64 dims)
        float s[2][4][4];
        #pragma unroll
        for (int h = 0; h < 2; h++)
            #pragma unroll
            for (int nt = 0; nt < 4; nt++)
                #pragma unroll
                for (int r = 0; r < 4; r++) s[h][nt][r] = 0.f;
        #pragma unroll
        for (int ks = 0; ks < 4; ks++) {
            uint32_t kb[4][2];
            ldsm_x4(kb[0][0], kb[0][1], kb[1][0], kb[1][1], kS + ks * 32);
            ldsm_x4(kb[2][0], kb[2][1], kb[3][0], kb[3][1], kS + 16 * 144 + ks * 32);
            #pragma unroll
            for (int h = 0; h < 2; h++)
                #pragma unroll
                for (int nt = 0; nt < 4; nt++)
                    mma_f16(s[h][nt], qf[h][ks], kb[nt][0], kb[nt][1]);
        }

        // mask + online softmax per half (log2 domain, exp2f)
        float alpha[2][2];
        #pragma unroll
        for (int h = 0; h < 2; h++) {
            float mx0 = -1e30f, mx1 = -1e30f;
            #pragma unroll
            for (int nt = 0; nt < 4; nt++) {
                int c = nt * 8 + 2 * tg;
                if (msk[st][c] == 0)     { s[h][nt][0] = -1e30f; s[h][nt][2] = -1e30f; }
                if (msk[st][c + 1] == 0) { s[h][nt][1] = -1e30f; s[h][nt][3] = -1e30f; }
                mx0 = fmaxf(mx0, fmaxf(s[h][nt][0], s[h][nt][1]));
                mx1 = fmaxf(mx1, fmaxf(s[h][nt][2], s[h][nt][3]));
            }
            mx0 = fmaxf(mx0, __shfl_xor_sync(0xffffffffu, mx0, 1));
            mx0 = fmaxf(mx0, __shfl_xor_sync(0xffffffffu, mx0, 2));
            mx1 = fmaxf(mx1, __shfl_xor_sync(0xffffffffu, mx1, 1));
            mx1 = fmaxf(mx1, __shfl_xor_sync(0xffffffffu, mx1, 2));

            float mn0 = fmaxf(mprev[h][0], mx0), mn1 = fmaxf(mprev[h][1], mx1);
            alpha[h][0] = exp2f(mprev[h][0] - mn0);
            alpha[h][1] = exp2f(mprev[h][1] - mn1);

            float ps0 = 0.f, ps1 = 0.f;
            #pragma unroll
            for (int nt = 0; nt < 4; nt++) {
                float e00 = exp2f(s[h][nt][0] - mn0);
                float e01 = exp2f(s[h][nt][1] - mn0);
                float e10 = exp2f(s[h][nt][2] - mn1);
                float e11 = exp2f(s[h][nt][3] - mn1);
                ps0 += e00 + e01;
                ps1 += e10 + e11;
                int r = h * 64 + warp * 16 + g;
                Ps[r][nt * 4 + tg]     = pack_half2(e00, e01);
                Ps[r + 8][nt * 4 + tg] = pack_half2(e10, e11);
            }
            lsum[h][0] = lsum[h][0] * alpha[h][0] + ps0;
            lsum[h][1] = lsum[h][1] * alpha[h][1] + ps1;
            mprev[h][0] = mn0; mprev[h][1] = mn1;
        }
        __syncwarp();   // P writes visible before ldmatrix reads (warp-local rows)

        // O = O*alpha + P V  (2 k16 steps over 32 keys)
        #pragma unroll
        for (int h = 0; h < 2; h++)
            #pragma unroll
            for (int nt = 0; nt < 8; nt++) {
                o[h][nt][0] *= alpha[h][0]; o[h][nt][1] *= alpha[h][0];
                o[h][nt][2] *= alpha[h][1]; o[h][nt][3] *= alpha[h][1];
            }
        #pragma unroll
        for (int ks = 0; ks < 2; ks++) {
            uint32_t vb[8][2];
            #pragma unroll
            for (int ntp = 0; ntp < 4; ntp++)
                ldsm_x4_t(vb[2 * ntp][0], vb[2 * ntp][1], vb[2 * ntp + 1][0], vb[2 * ntp + 1][1],
                          vS + ks * 16 * 144 + ntp * 32);
            #pragma unroll
            for (int h = 0; h < 2; h++) {
                uint32_t af[4];
                ldsm_x4(af[0], af[1], af[2], af[3],
                        pAddr0 + (h * 64 + warp * 16) * 80 + ks * 32);
                #pragma unroll
                for (int nt = 0; nt < 8; nt++)
                    mma_f16(o[h][nt], af, vb[nt][0], vb[nt][1]);
            }
        }
        __syncwarp();
    }

    #pragma unroll
    for (int h = 0; h < 2; h++) {
        float l0 = lsum[h][0], l1 = lsum[h][1];
        l0 += __shfl_xor_sync(0xffffffffu, l0, 1);
        l0 += __shfl_xor_sync(0xffffffffu, l0, 2);
        l1 += __shfl_xor_sync(0xffffffffu, l1, 1);
        l1 += __shfl_xor_sync(0xffffffffu, l1, 2);
        float inv0 = 1.0f / l0, inv1 = 1.0f / l1;

        int r0 = q0 + h * 64 + warp * 16 + g;
        #pragma unroll
        for (int nt = 0; nt < 8; nt++) {
            int c = qcol + nt * 8 + 2 * tg;
            *reinterpret_cast<__half2*>(out16 + (base + r0) * DD + c) =
                __floats2half2_rn(o[h][nt][0] * inv0, o[h][nt][1] * inv0);
            *reinterpret_cast<__half2*>(out16 + (base + r0 + 8) * DD + c) =
                __floats2half2_rn(o[h][nt][2] * inv1, o[h][nt][3] * inv1);
        }
    }
}

// ---------------- residual add + LayerNorm (fp32 + optional fp16 out) -----
__device__ __forceinline__ float block_reduce_256(float v, float* red) {
    __syncthreads();
    int t = threadIdx.x;
    #pragma unroll
    for (int o = 16; o > 0; o >>= 1) v += __shfl_down_sync(0xffffffffu, v, o);
    if ((t & 31) == 0) red[t >> 5] = v;
    __syncthreads();
    if (t < 8) {
        v = red[t];
        #pragma unroll
        for (int o = 4; o > 0; o >>= 1) v += __shfl_down_sync(0xffu, v, o);
        if (t == 0) red[0] = v;
    }
    __syncthreads();
    return red[0];
}

template<bool OUT16>
__global__ void add_ln_kernel(const float* __restrict__ A,
                              float* __restrict__ X,
                              __half* __restrict__ X16,
                              const float* __restrict__ g,
                              const float* __restrict__ bt) {
    __shared__ float red[32];
    int r = blockIdx.x, t = threadIdx.x;
    const float* a = A + (size_t)r * DD;
    float* x = X + (size_t)r * DD;
    int d0 = t * 4;
    float4 av = *reinterpret_cast<const float4*>(a + d0);
    float4 xv = *reinterpret_cast<const float4*>(x + d0);
    float v[4] = {av.x + xv.x, av.y + xv.y, av.z + xv.z, av.w + xv.w};
    float sum = v[0] + v[1] + v[2] + v[3];
    sum = block_reduce_256(sum, red);
    float mu = sum * (1.0f / DD);
    float vs = 0.f;
    #pragma unroll
    for (int i = 0; i < 4; i++) { float dl = v[i] - mu; vs += dl * dl; }
    vs = block_reduce_256(vs, red);
    float rs = rsqrtf(vs * (1.0f / DD) + 1e-5f);
    float o[4];
    #pragma unroll
    for (int i = 0; i < 4; i++)
        o[i] = (v[i] - mu) * rs * g[d0 + i] + bt[d0 + i];
    *reinterpret_cast<float4*>(x + d0) = make_float4(o[0], o[1], o[2], o[3]);
    if (OUT16) {
        __half* x16 = X16 + (size_t)r * DD + d0;
        *reinterpret_cast<__half2*>(x16)     = __floats2half2_rn(o[0], o[1]);
        *reinterpret_cast<__half2*>(x16 + 2) = __floats2half2_rn(o[2], o[3]);
    }
}

// ---------------- masked max-pool over sequence ----------------
__global__ void pool_partial_kernel(const float* __restrict__ X,
                                    const int* __restrict__ mask,
                                    float* __restrict__ part) {
    int b = blockIdx.y, ch = blockIdx.x;
    int d = threadIdx.x;
    float m = -INFINITY;
    for (int s = 0; s < 128; s++) {
        int srow = ch * 128 + s;
        float val = X[((size_t)b * SS + srow) * DD + d];
        if (mask[b * SS + srow] != 0) m = fmaxf(m, val);
    }
    part[((size_t)b * 16 + ch) * DD + d] = m;
}

__global__ void pool_final_kernel(const float* __restrict__ part,
                                  float* __restrict__ pooled) {
    int b = blockIdx.x, d = threadIdx.x;
    float m = -INFINITY;
    for (int c = 0; c < 16; c++)
        m = fmaxf(m, part[((size_t)b * 16 + c) * DD + d]);
    pooled[b * DD + d] = m;
}

// ---------------- small head FC ----------------
__global__ void head_fc_kernel(const float* __restrict__ in,
                               const float* __restrict__ W,
                               const float* __restrict__ bias,
                               float* __restrict__ out,
                               int K, int apply_gelu) {
    __shared__ float red[4];
    int n = blockIdx.x, b = blockIdx.y, t = threadIdx.x;
    int N = gridDim.x;
    const float* ip = in + (size_t)b * K;
    const float* wp = W + (size_t)n * K;
    float s = 0.f;
    for (int k = t; k < K; k += 128) s += ip[k] * wp[k];
    #pragma unroll
    for (int o = 16; o > 0; o >>= 1) s += __shfl_down_sync(0xffffffffu, s, o);
    if ((t & 31) == 0) red[t >> 5] = s;
    __syncthreads();
    if (t == 0) {
        float v = red[0] + red[1] + red[2] + red[3] + bias[n];
        if (apply_gelu) v = gelu_exact(v);
        out[b * N + n] = v;
    }
}

// ---------------- launch ----------------
extern "C" void kernel_launch(void* const* d_in, const int* in_sizes, int n_in,
                              void* d_out, int out_size) {
    const int*   x_ids  = (const int*)d_in[0];
    const int*   mask   = (const int*)d_in[1];
    const float* emb    = (const float*)d_in[2];
    const float* qkv_w  = (const float*)d_in[3];
    const float* fc_w   = (const float*)d_in[4];
    const float* fc_b   = (const float*)d_in[5];
    const float* ln1_g  = (const float*)d_in[6];
    const float* ln1_b  = (const float*)d_in[7];
    const float* ffn_w1 = (const float*)d_in[8];
    const float* ffn_b1 = (const float*)d_in[9];
    const float* ffn_w2 = (const float*)d_in[10];
    const float* ffn_b2 = (const float*)d_in[11];
    const float* ln2_g  = (const float*)d_in[12];
    const float* ln2_b  = (const float*)d_in[13];
    const float* pr_w1  = (const float*)d_in[14];
    const float* pr_b1  = (const float*)d_in[15];
    const float* pr_w2  = (const float*)d_in[16];
    const float* pr_b2  = (const float*)d_in[17];
    float* out = (float*)d_out;

    float *X, *O, *part, *pool, *hh;
    __half *X16, *QKV16, *AO16, *H16, *Wq16, *Wf16, *W116, *W216;
    cudaGetSymbolAddress((void**)&X,     g_X);
    cudaGetSymbolAddress((void**)&O,     g_O);
    cudaGetSymbolAddress((void**)&X16,   g_X16);
    cudaGetSymbolAddress((void**)&QKV16, g_QKV16);
    cudaGetSymbolAddress((void**)&AO16,  g_AO16);
    cudaGetSymbolAddress((void**)&H16,   g_H16);
    cudaGetSymbolAddress((void**)&Wq16,  g_Wq16);
    cudaGetSymbolAddress((void**)&Wf16,  g_Wf16);
    cudaGetSymbolAddress((void**)&W116,  g_W116);
    cudaGetSymbolAddress((void**)&W216,  g_W216);
    cudaGetSymbolAddress((void**)&part,  g_part);
    cudaGetSymbolAddress((void**)&pool,  g_pool);
    cudaGetSymbolAddress((void**)&hh,    g_hh);

    // 0. convert all weights to fp16 (single kernel)
    {
        int chunks = (3 * DD * DD + DD * DD + FFN * DD + DD * FFN) / 4;
        f2h_all_kernel<<<(chunks + 255) / 256, 256>>>(
            qkv_w, Wq16, fc_w, Wf16, ffn_w1, W116, ffn_w2, W216);
    }

    // 1. embedding + positional encoding (fp32 + fp16)
    embed_pe_kernel<<<(NTOK * (DD / 2)) / 256, 256>>>(x_ids, emb, X, X16);

    // 2. QKV projection -> fp16
    gemm_f16_kernel<0, true><<<dim3(3 * DD / 128, NTOK / 128), 128>>>(
        X16, Wq16, nullptr, nullptr, QKV16, NTOK, 3 * DD, DD);

    // 3. attention (fp16 MMA; log2-domain softmax)
    flash_f16_kernel<<<dim3(SS / 128, HH, BB), 128>>>(QKV16, mask, AO16);

    // 4. output projection (+bias) -> fp32
    gemm_f16_kernel<1, false><<<dim3(DD / 128, NTOK / 128), 128>>>(
        AO16, Wf16, fc_b, O, nullptr, NTOK, DD, DD);

    // 5. residual + LN1 (fp32 X + fp16 copy)
    add_ln_kernel<true><<<NTOK, 256>>>(O, X, X16, ln1_g, ln1_b);

    // 6. FFN up (+bias, gelu) -> fp16
    gemm_f16_kernel<2, true><<<dim3(FFN / 128, NTOK / 128), 128>>>(
        X16, W116, ffn_b1, nullptr, H16, NTOK, FFN, DD);

    // 7. FFN down (+bias) -> fp32
    gemm_f16_kernel<1, false><<<dim3(DD / 128, NTOK / 128), 128>>>(
        H16, W216, ffn_b2, O, nullptr, NTOK, DD, FFN);

    // 8. residual + LN2 (fp32 only)
    add_ln_kernel<false><<<NTOK, 256>>>(O, X, nullptr, ln2_g, ln2_b);

    // 9. masked max-pool
    pool_partial_kernel<<<dim3(16, BB), 1024>>>(X, mask, part);
    pool_final_kernel<<<BB, 1024>>>(part, pool);

    // 10. prediction head
    head_fc_kernel<<<dim3(DD, BB), 128>>>(pool, pr_w1, pr_b1, hh, DD, 1);
    head_fc_kernel<<<dim3(10, BB), 128>>>(hh, pr_w2, pr_b2, out, DD, 0);
}